// round 8
// baseline (speedup 1.0000x reference)
#include <cuda_runtime.h>
#include <cuda_bf16.h>
#include <math.h>
#include <float.h>
#include <stdint.h>

// Problem constants
#define BB    32
#define NNODE 256
#define DD    512
#define HH    8
#define EE    1024
#define EDIM  256
#define GDIM  64
#define HDIM  64
#define BNROWS (BB*NNODE)   // 8192
#define DFF   2048

// ---------------- scratch (device globals; no runtime alloc) ----------------
__device__ float g_q  [BNROWS*DD];
__device__ float g_k  [BNROWS*DD];
__device__ float g_v  [BNROWS*DD];
__device__ float g_x2 [BNROWS*DD];
__device__ float g_ebias[BB*EE*HH];
__device__ int   g_wmap[BB*NNODE*NNODE];
__device__ float g_bm[(size_t)BB*HH*NNODE*NNODE];

// pre-split bf16 hi/lo activation + weight buffers
__device__ __nv_bfloat16 g_xnh [BNROWS*DD],  g_xnl [BNROWS*DD];
__device__ __nv_bfloat16 g_atth[BNROWS*DD],  g_attl[BNROWS*DD];
__device__ __nv_bfloat16 g_ln2h[BNROWS*DD],  g_ln2l[BNROWS*DD];
__device__ __nv_bfloat16 g_h1h [BNROWS*DFF], g_h1l [BNROWS*DFF];
__device__ __nv_bfloat16 g_wqh[DD*DD], g_wql[DD*DD];
__device__ __nv_bfloat16 g_wkh[DD*DD], g_wkl[DD*DD];
__device__ __nv_bfloat16 g_wvh[DD*DD], g_wvl[DD*DD];
__device__ __nv_bfloat16 g_woh[DD*DD], g_wol[DD*DD];
__device__ __nv_bfloat16 g_w1h[DFF*DD], g_w1l[DFF*DD];
__device__ __nv_bfloat16 g_w2h[DD*DFF], g_w2l[DD*DFF];

// ---------------- fp32 -> bf16 hi/lo split ----------------
__global__ void split_kernel(const float* __restrict__ src, __nv_bfloat16* __restrict__ h,
                             __nv_bfloat16* __restrict__ l, int n) {
    int i = blockIdx.x * 256 + threadIdx.x;
    if (i < n) {
        float v = src[i];
        __nv_bfloat16 hh = __float2bfloat16_rn(v);
        h[i] = hh;
        l[i] = __float2bfloat16_rn(v - __bfloat162float(hh));
    }
}

// ---------------- LayerNorm -> bf16 hi/lo ----------------
__global__ void ln_bf16_kernel(const float* __restrict__ x, const float* __restrict__ g,
                               const float* __restrict__ b, __nv_bfloat16* __restrict__ yh,
                               __nv_bfloat16* __restrict__ yl) {
    int row = blockIdx.x;
    const float* xr = x + (size_t)row * DD;
    int tid = threadIdx.x; // 128
    float v[4];
    float s = 0.f, s2 = 0.f;
#pragma unroll
    for (int i = 0; i < 4; i++) {
        v[i] = xr[tid + i * 128];
        s += v[i]; s2 += v[i] * v[i];
    }
    __shared__ float rs[4], rs2[4];
    for (int o = 16; o; o >>= 1) {
        s  += __shfl_xor_sync(~0u, s,  o);
        s2 += __shfl_xor_sync(~0u, s2, o);
    }
    int w = tid >> 5;
    if ((tid & 31) == 0) { rs[w] = s; rs2[w] = s2; }
    __syncthreads();
    s  = rs[0] + rs[1] + rs[2] + rs[3];
    s2 = rs2[0] + rs2[1] + rs2[2] + rs2[3];
    float mean = s * (1.f / DD);
    float var  = s2 * (1.f / DD) - mean * mean;
    float r = rsqrtf(var + 1e-5f);
#pragma unroll
    for (int i = 0; i < 4; i++) {
        int c = tid + i * 128;
        float y = (v[i] - mean) * r * g[c] + b[c];
        __nv_bfloat16 hh = __float2bfloat16_rn(y);
        yh[(size_t)row * DD + c] = hh;
        yl[(size_t)row * DD + c] = __float2bfloat16_rn(y - __bfloat162float(hh));
    }
}

// ========== pipelined tensor-core GEMM: 512 thr, 16 warps 4x4, 3-stage cp.async ==========
// C = A(MxK) @ W(NoutxK)^T + bias. EPI: 0=bias->f32, 1=+res->f32, 2=silu->bf16 hi/lo, 3=+res,*rowscale->f32
#define PITCH 40   // bf16 per smem row (32 data + 8 pad) = 80 B
#define GSTAGE 40960
#define GSMEMB (3 * GSTAGE)

#define CP16(dst, src) \
    asm volatile("cp.async.cg.shared.global [%0], [%1], 16;" :: "r"(dst), "l"(src))

__device__ __forceinline__ void ldsm4(uint32_t a, uint32_t& r0, uint32_t& r1,
                                      uint32_t& r2, uint32_t& r3) {
    asm volatile("ldmatrix.sync.aligned.m8n8.x4.shared.b16 {%0,%1,%2,%3}, [%4];"
                 : "=r"(r0), "=r"(r1), "=r"(r2), "=r"(r3) : "r"(a));
}

__device__ __forceinline__ void mma16816(float (&d)[4], const uint32_t (&a)[4],
                                         const uint32_t* b) {
    asm volatile("mma.sync.aligned.m16n8k16.row.col.f32.bf16.bf16.f32 "
                 "{%0,%1,%2,%3}, {%4,%5,%6,%7}, {%8,%9}, {%0,%1,%2,%3};"
                 : "+f"(d[0]), "+f"(d[1]), "+f"(d[2]), "+f"(d[3])
                 : "r"(a[0]), "r"(a[1]), "r"(a[2]), "r"(a[3]), "r"(b[0]), "r"(b[1]));
}

template<int EPI>
__global__ void __launch_bounds__(512, 1)
gemm_bf16(const __nv_bfloat16* __restrict__ Ah_g, const __nv_bfloat16* __restrict__ Al_g,
          const __nv_bfloat16* __restrict__ Bh_g, const __nv_bfloat16* __restrict__ Bl_g,
          const float* __restrict__ bias, const float* __restrict__ res,
          const float* __restrict__ rowscale, float* __restrict__ C,
          __nv_bfloat16* __restrict__ Ch, __nv_bfloat16* __restrict__ Cl,
          int M, int Nout, int K) {
    extern __shared__ __align__(16) __nv_bfloat16 sm[];
    uint32_t smBase = (uint32_t)__cvta_generic_to_shared(sm);

    int tid = threadIdx.x;               // 512 = 16 warps (4x4)
    int warp = tid >> 5, lane = tid & 31;
    int wm = warp >> 2, wn = warp & 3;
    int bm0 = blockIdx.y * 128, bn0 = blockIdx.x * 128;

    float acc[2][4][4];
#pragma unroll
    for (int i = 0; i < 2; i++)
#pragma unroll
        for (int j = 0; j < 4; j++)
#pragma unroll
            for (int r = 0; r < 4; r++) acc[i][j][r] = 0.f;

    // cp.async: per array 512 chunks(16B) = 128 rows x 4 chunks.
    // tid<256 -> Ah/Al; tid>=256 -> Bh/Bl; each thread 2 chunks per array.
    int cc  = tid & 255;
    int grp = tid >> 8;

    // ldmatrix per-lane address components (byte offsets within a stage)
    int a_r  = lane & 15;
    int a_cb = (lane >> 4) << 4;
    uint32_t aOffH = (uint32_t)((wm * 32 + a_r) * (PITCH * 2) + a_cb);
    int b_r  = ((lane >> 4) & 1) * 8 + (lane & 7);
    int b_cb = ((lane >> 3) & 1) << 4;
    uint32_t bOffH = (uint32_t)((wn * 32 + b_r) * (PITCH * 2) + b_cb);

    auto issue_tile = [&](int s, int k0) {
        uint32_t st = smBase + (uint32_t)s * GSTAGE;
#pragma unroll
        for (int r = 0; r < 2; r++) {
            int c = cc + r * 256;            // 0..511
            int crow = c >> 2;               // 0..127
            int cb   = (c & 3) << 4;         // 0,16,32,48 bytes
            uint32_t so = (uint32_t)(crow * PITCH * 2 + cb);
            if (grp == 0) {
                size_t ga = (size_t)(bm0 + crow) * K + k0 + (c & 3) * 8;
                CP16(st + so,          Ah_g + ga);
                CP16(st + 10240 + so,  Al_g + ga);
            } else {
                size_t gb = (size_t)(bn0 + crow) * K + k0 + (c & 3) * 8;
                CP16(st + 20480 + so,  Bh_g + gb);
                CP16(st + 30720 + so,  Bl_g + gb);
            }
        }
    };

    int ktiles = K >> 5;
    issue_tile(0, 0);
    asm volatile("cp.async.commit_group;");
    issue_tile(1, 32);
    asm volatile("cp.async.commit_group;");
    issue_tile(2, 64);
    asm volatile("cp.async.commit_group;");

#pragma unroll 1
    for (int t = 0; t < ktiles; t++) {
        int s = t % 3;
        asm volatile("cp.async.wait_group 2;");
        __syncthreads();

        uint32_t pAh = smBase + (uint32_t)s * GSTAGE;
        uint32_t pAl = pAh + 10240u;
        uint32_t pBh = pAh + 20480u;
        uint32_t pBl = pAh + 30720u;
#pragma unroll
        for (int ks = 0; ks < 2; ks++) {
            uint32_t kb = (uint32_t)(ks * 32);
            uint32_t ah[2][4], al[2][4], bh[4][2], bl[4][2];
#pragma unroll
            for (int mi = 0; mi < 2; mi++) {
                uint32_t off = aOffH + (uint32_t)(mi * 16 * PITCH * 2) + kb;
                ldsm4(pAh + off, ah[mi][0], ah[mi][1], ah[mi][2], ah[mi][3]);
                ldsm4(pAl + off, al[mi][0], al[mi][1], al[mi][2], al[mi][3]);
            }
#pragma unroll
            for (int bp = 0; bp < 2; bp++) {
                uint32_t off = bOffH + (uint32_t)(bp * 16 * PITCH * 2) + kb;
                ldsm4(pBh + off, bh[2*bp][0], bh[2*bp][1], bh[2*bp+1][0], bh[2*bp+1][1]);
                ldsm4(pBl + off, bl[2*bp][0], bl[2*bp][1], bl[2*bp+1][0], bl[2*bp+1][1]);
            }
#pragma unroll
            for (int mi = 0; mi < 2; mi++)
#pragma unroll
                for (int ni = 0; ni < 4; ni++) {
                    mma16816(acc[mi][ni], ah[mi], bh[ni]);
                    mma16816(acc[mi][ni], ah[mi], bl[ni]);
                    mma16816(acc[mi][ni], al[mi], bh[ni]);
                }
        }
        __syncthreads();
        int nk = (t + 3) << 5;
        if (nk < K) issue_tile(s, nk);
        asm volatile("cp.async.commit_group;");
    }

    // epilogue
    int qr = lane >> 2, qc = (lane & 3) << 1;
#pragma unroll
    for (int mi = 0; mi < 2; mi++) {
        int m0 = bm0 + wm * 32 + mi * 16 + qr;
#pragma unroll
        for (int ni = 0; ni < 4; ni++) {
            int n = bn0 + wn * 32 + ni * 8 + qc;
            float b0 = bias[n], b1 = bias[n + 1];
#pragma unroll
            for (int rr = 0; rr < 2; rr++) {
                int m = m0 + rr * 8;
                float v0 = acc[mi][ni][rr * 2 + 0] + b0;
                float v1 = acc[mi][ni][rr * 2 + 1] + b1;
                if (EPI == 1 || EPI == 3) {
                    v0 += res[(size_t)m * Nout + n];
                    v1 += res[(size_t)m * Nout + n + 1];
                }
                if (EPI == 2) {
                    v0 = v0 / (1.f + expf(-v0));
                    v1 = v1 / (1.f + expf(-v1));
                    __nv_bfloat16 h0 = __float2bfloat16_rn(v0);
                    __nv_bfloat16 h1 = __float2bfloat16_rn(v1);
                    __nv_bfloat162 hh(h0, h1);
                    __nv_bfloat162 ll(__float2bfloat16_rn(v0 - __bfloat162float(h0)),
                                      __float2bfloat16_rn(v1 - __bfloat162float(h1)));
                    *(__nv_bfloat162*)(Ch + (size_t)m * Nout + n) = hh;
                    *(__nv_bfloat162*)(Cl + (size_t)m * Nout + n) = ll;
                } else {
                    if (EPI == 3) { float rsc = rowscale[m]; v0 *= rsc; v1 *= rsc; }
                    *(float2*)(C + (size_t)m * Nout + n) = make_float2(v0, v1);
                }
            }
        }
    }
}

// ---------------- Edge bias: one warp per (b,e) ----------------
__global__ void edge_bias_kernel(const float* __restrict__ rel, const float* __restrict__ geo,
                                 const float* __restrict__ W_eb, const float* __restrict__ b_eb,
                                 const float* __restrict__ geog, const float* __restrict__ geob,
                                 const float* __restrict__ W_geo, const float* __restrict__ b_geo) {
    int warp = (blockIdx.x * blockDim.x + threadIdx.x) >> 5;
    int lane = threadIdx.x & 31;
    if (warp >= BB * EE) return;
    const float* re = rel + (size_t)warp * EDIM;
    const float* ge = geo + (size_t)warp * GDIM;
    float acc[8] = {0, 0, 0, 0, 0, 0, 0, 0};
#pragma unroll
    for (int it = 0; it < 8; it++) {
        int c = (it << 5) + lane;
        float xv = re[c];
#pragma unroll
        for (int h = 0; h < 8; h++) acc[h] += xv * W_eb[h * EDIM + c];
    }
    float g0 = ge[lane], g1 = ge[lane + 32];
    float s = g0 + g1, s2 = g0 * g0 + g1 * g1;
    for (int o = 16; o; o >>= 1) {
        s  += __shfl_xor_sync(~0u, s,  o);
        s2 += __shfl_xor_sync(~0u, s2, o);
    }
    float mean = s * (1.f / 64.f);
    float var  = s2 * (1.f / 64.f) - mean * mean;
    float r = rsqrtf(var + 1e-5f);
    float n0 = (g0 - mean) * r * geog[lane]      + geob[lane];
    float n1 = (g1 - mean) * r * geog[lane + 32] + geob[lane + 32];
#pragma unroll
    for (int h = 0; h < 8; h++)
        acc[h] += n0 * W_geo[h * GDIM + lane] + n1 * W_geo[h * GDIM + lane + 32];
#pragma unroll
    for (int h = 0; h < 8; h++) {
        float v = acc[h];
        for (int o = 16; o; o >>= 1) v += __shfl_xor_sync(~0u, v, o);
        if (lane == h) g_ebias[(size_t)warp * HH + h] = v + b_eb[h] + b_geo[h];
    }
}

// ---------------- winner map + scatter + fill ----------------
__global__ void wmap_init_kernel() {
    int idx = blockIdx.x * 256 + threadIdx.x;
    g_wmap[idx] = -1;
}

__global__ void wmap_scatter_kernel(const int* __restrict__ edges, const float* __restrict__ emask) {
    int t = blockIdx.x * 256 + threadIdx.x;
    if (t >= BB * EE) return;
    int b = t >> 10, e = t & 1023;
    if (emask[t] > 0.5f) {
        int s = min(max(edges[2 * t], 0), NNODE - 1);
        int d = min(max(edges[2 * t + 1], 0), NNODE - 1);
        atomicMax(&g_wmap[b * 65536 + s * 256 + d], e);
        atomicMax(&g_wmap[b * 65536 + d * 256 + s], e + EE);
    }
}

__global__ void bm_fill_kernel(const float* __restrict__ nmask) {
    int idx = blockIdx.x * 256 + threadIdx.x;
    int j = idx & 255, i = (idx >> 8) & 255, b = idx >> 16;
    int w = g_wmap[idx];
    bool ok = (nmask[b * 256 + i] != 0.f) && (nmask[b * 256 + j] != 0.f) && (w >= 0 || i == j);
    float* bm = g_bm + (size_t)b * HH * 65536 + i * 256 + j;
    if (!ok) {
#pragma unroll
        for (int h = 0; h < HH; h++) bm[(size_t)h * 65536] = -FLT_MAX;
    } else if (w < 0) {
#pragma unroll
        for (int h = 0; h < HH; h++) bm[(size_t)h * 65536] = 0.f;
    } else {
        int e = (w >= EE) ? w - EE : w;
        const float* eb = g_ebias + ((size_t)b * EE + e) * HH;
#pragma unroll
        for (int h = 0; h < HH; h++) bm[(size_t)h * 65536] = eb[h];
    }
}

// ---------------- fused attention: one block per (b,h); warp per query row ----------------
#define KT_PITCH 260
__global__ void attn_kernel() {
    extern __shared__ float smem[];
    float* kt = smem;
    float* vs = kt + 64 * KT_PITCH;
    float* qs = vs + 256 * 64;
    float* ps = qs + 8 * 64;

    int bh = blockIdx.x;
    int b = bh >> 3, h = bh & 7;
    int tid = threadIdx.x;
    int w = tid >> 5, lane = tid & 31;

    for (int idx = tid; idx < 256 * 64; idx += 256) {
        int j = idx >> 6, d = idx & 63;
        size_t off = (size_t)(b * NNODE + j) * DD + h * HDIM + d;
        kt[d * KT_PITCH + j] = g_k[off];
        vs[j * 64 + d]       = g_v[off];
    }
    __syncthreads();

    const float* bmB = g_bm + (size_t)bh * 65536;
    float* psw = ps + w * 256;
    float* qsw = qs + w * 64;

    for (int i = w * 32; i < w * 32 + 32; i++) {
        size_t qoff = (size_t)(b * NNODE + i) * DD + h * HDIM;
        qsw[lane]      = g_q[qoff + lane];
        qsw[lane + 32] = g_q[qoff + lane + 32];
        __syncwarp();

        float4 bm0 = *(const float4*)&bmB[i * 256 + (lane << 2)];
        float4 bm1 = *(const float4*)&bmB[i * 256 + 128 + (lane << 2)];

        float s[8] = {0, 0, 0, 0, 0, 0, 0, 0};
#pragma unroll 8
        for (int d = 0; d < 64; d++) {
            float qd = qsw[d];
            float4 k0 = *(const float4*)&kt[d * KT_PITCH + (lane << 2)];
            float4 k1 = *(const float4*)&kt[d * KT_PITCH + 128 + (lane << 2)];
            s[0] += qd * k0.x; s[1] += qd * k0.y; s[2] += qd * k0.z; s[3] += qd * k0.w;
            s[4] += qd * k1.x; s[5] += qd * k1.y; s[6] += qd * k1.z; s[7] += qd * k1.w;
        }
        float sc[8];
        const float* bmv0 = &bm0.x;
        const float* bmv1 = &bm1.x;
#pragma unroll
        for (int r = 0; r < 4; r++) {
            sc[r]     = (bmv0[r] == -FLT_MAX) ? -FLT_MAX : s[r]     * 0.125f + bmv0[r];
            sc[4 + r] = (bmv1[r] == -FLT_MAX) ? -FLT_MAX : s[4 + r] * 0.125f + bmv1[r];
        }
        float mx = sc[0];
#pragma unroll
        for (int r = 1; r < 8; r++) mx = fmaxf(mx, sc[r]);
        for (int o = 16; o; o >>= 1) mx = fmaxf(mx, __shfl_xor_sync(~0u, mx, o));
        float p[8], sum = 0.f;
#pragma unroll
        for (int r = 0; r < 8; r++) { p[r] = expf(sc[r] - mx); sum += p[r]; }
        for (int o = 16; o; o >>= 1) sum += __shfl_xor_sync(~0u, sum, o);
        float inv = 1.f / sum;

        *(float4*)&psw[lane << 2]         = make_float4(p[0], p[1], p[2], p[3]);
        *(float4*)&psw[128 + (lane << 2)] = make_float4(p[4], p[5], p[6], p[7]);
        __syncwarp();

        int d0 = lane << 1;
        float o0 = 0.f, o1 = 0.f;
#pragma unroll 4
        for (int j0 = 0; j0 < 256; j0 += 4) {
            float4 p4 = *(const float4*)&psw[j0];
            float2 v0 = *(const float2*)&vs[(j0 + 0) * 64 + d0];
            float2 v1 = *(const float2*)&vs[(j0 + 1) * 64 + d0];
            float2 v2 = *(const float2*)&vs[(j0 + 2) * 64 + d0];
            float2 v3 = *(const float2*)&vs[(j0 + 3) * 64 + d0];
            o0 += p4.x * v0.x + p4.y * v1.x + p4.z * v2.x + p4.w * v3.x;
            o1 += p4.x * v0.y + p4.y * v1.y + p4.z * v2.y + p4.w * v3.y;
        }
        o0 *= inv; o1 *= inv;
        __nv_bfloat16 h0 = __float2bfloat16_rn(o0);
        __nv_bfloat16 h1 = __float2bfloat16_rn(o1);
        __nv_bfloat162 hh(h0, h1);
        __nv_bfloat162 ll(__float2bfloat16_rn(o0 - __bfloat162float(h0)),
                          __float2bfloat16_rn(o1 - __bfloat162float(h1)));
        *(__nv_bfloat162*)&g_atth[qoff + d0] = hh;
        *(__nv_bfloat162*)&g_attl[qoff + d0] = ll;
        __syncwarp();
    }
}

// ---------------- host launcher ----------------
extern "C" void kernel_launch(void* const* d_in, const int* in_sizes, int n_in,
                              void* d_out, int out_size) {
    const float* x     = (const float*)d_in[0];
    const float* nmask = (const float*)d_in[1];
    const int*   edges = (const int*)  d_in[2];
    const float* emask = (const float*)d_in[3];
    const float* rel   = (const float*)d_in[4];
    const float* geo   = (const float*)d_in[5];
    const float* Wq = (const float*)d_in[6];  const float* bq = (const float*)d_in[7];
    const float* Wk = (const float*)d_in[8];  const float* bk = (const float*)d_in[9];
    const float* Wv = (const float*)d_in[10]; const float* bv = (const float*)d_in[11];
    const float* W_eb = (const float*)d_in[12]; const float* b_eb = (const float*)d_in[13];
    const float* geog = (const float*)d_in[14]; const float* geob = (const float*)d_in[15];
    const float* W_geo = (const float*)d_in[16]; const float* b_geo = (const float*)d_in[17];
    const float* W_out = (const float*)d_in[18]; const float* b_out = (const float*)d_in[19];
    const float* ng = (const float*)d_in[20]; const float* nb = (const float*)d_in[21];
    const float* fg = (const float*)d_in[22]; const float* fb = (const float*)d_in[23];
    const float* W1 = (const float*)d_in[24]; const float* b1 = (const float*)d_in[25];
    const float* W2 = (const float*)d_in[26]; const float* b2 = (const float*)d_in[27];
    float* out = (float*)d_out;

    float *pq, *pk, *pv, *px2;
    cudaGetSymbolAddress((void**)&pq,  g_q);
    cudaGetSymbolAddress((void**)&pk,  g_k);
    cudaGetSymbolAddress((void**)&pv,  g_v);
    cudaGetSymbolAddress((void**)&px2, g_x2);
    __nv_bfloat16 *xnh, *xnl, *atth, *attl, *ln2h, *ln2l, *h1h, *h1l;
    __nv_bfloat16 *wqh, *wql, *wkh, *wkl, *wvh, *wvl, *woh, *wol, *w1h, *w1l, *w2h, *w2l;
    cudaGetSymbolAddress((void**)&xnh,  g_xnh);  cudaGetSymbolAddress((void**)&xnl,  g_xnl);
    cudaGetSymbolAddress((void**)&atth, g_atth); cudaGetSymbolAddress((void**)&attl, g_attl);
    cudaGetSymbolAddress((void**)&ln2h, g_ln2h); cudaGetSymbolAddress((void**)&ln2l, g_ln2l);
    cudaGetSymbolAddress((void**)&h1h,  g_h1h);  cudaGetSymbolAddress((void**)&h1l,  g_h1l);
    cudaGetSymbolAddress((void**)&wqh, g_wqh);   cudaGetSymbolAddress((void**)&wql, g_wql);
    cudaGetSymbolAddress((void**)&wkh, g_wkh);   cudaGetSymbolAddress((void**)&wkl, g_wkl);
    cudaGetSymbolAddress((void**)&wvh, g_wvh);   cudaGetSymbolAddress((void**)&wvl, g_wvl);
    cudaGetSymbolAddress((void**)&woh, g_woh);   cudaGetSymbolAddress((void**)&wol, g_wol);
    cudaGetSymbolAddress((void**)&w1h, g_w1h);   cudaGetSymbolAddress((void**)&w1l, g_w1l);
    cudaGetSymbolAddress((void**)&w2h, g_w2h);   cudaGetSymbolAddress((void**)&w2l, g_w2l);

    cudaFuncSetAttribute(gemm_bf16<0>, cudaFuncAttributeMaxDynamicSharedMemorySize, GSMEMB);
    cudaFuncSetAttribute(gemm_bf16<1>, cudaFuncAttributeMaxDynamicSharedMemorySize, GSMEMB);
    cudaFuncSetAttribute(gemm_bf16<2>, cudaFuncAttributeMaxDynamicSharedMemorySize, GSMEMB);
    cudaFuncSetAttribute(gemm_bf16<3>, cudaFuncAttributeMaxDynamicSharedMemorySize, GSMEMB);

    // 0) weight splits
    split_kernel<<<DD * DD / 256, 256>>>(Wq, wqh, wql, DD * DD);
    split_kernel<<<DD * DD / 256, 256>>>(Wk, wkh, wkl, DD * DD);
    split_kernel<<<DD * DD / 256, 256>>>(Wv, wvh, wvl, DD * DD);
    split_kernel<<<DD * DD / 256, 256>>>(W_out, woh, wol, DD * DD);
    split_kernel<<<DFF * DD / 256, 256>>>(W1, w1h, w1l, DFF * DD);
    split_kernel<<<DD * DFF / 256, 256>>>(W2, w2h, w2l, DD * DFF);
    // 1) pre-LN -> bf16 split
    ln_bf16_kernel<<<BNROWS, 128>>>(x, ng, nb, xnh, xnl);
    // 2) Q,K,V projections
    gemm_bf16<0><<<dim3(DD / 128, BNROWS / 128), 512, GSMEMB>>>(xnh, xnl, wqh, wql, bq, nullptr, nullptr, pq, nullptr, nullptr, BNROWS, DD, DD);
    gemm_bf16<0><<<dim3(DD / 128, BNROWS / 128), 512, GSMEMB>>>(xnh, xnl, wkh, wkl, bk, nullptr, nullptr, pk, nullptr, nullptr, BNROWS, DD, DD);
    gemm_bf16<0><<<dim3(DD / 128, BNROWS / 128), 512, GSMEMB>>>(xnh, xnl, wvh, wvl, bv, nullptr, nullptr, pv, nullptr, nullptr, BNROWS, DD, DD);
    // 3) per-edge bias
    edge_bias_kernel<<<(BB * EE) / 8, 256>>>(rel, geo, W_eb, b_eb, geog, geob, W_geo, b_geo);
    // 4) parallel ordered scatter
    wmap_init_kernel<<<(BB * NNODE * NNODE) / 256, 256>>>();
    wmap_scatter_kernel<<<(BB * EE) / 256, 256>>>(edges, emask);
    bm_fill_kernel<<<(BB * NNODE * NNODE) / 256, 256>>>(nmask);
    // 5) fused attention (writes bf16 hi/lo)
    int attn_smem = (64 * KT_PITCH + 256 * 64 + 8 * 64 + 8 * 256) * 4;
    cudaFuncSetAttribute(attn_kernel, cudaFuncAttributeMaxDynamicSharedMemorySize, attn_smem);
    attn_kernel<<<BB * HH, 256, attn_smem>>>();
    // 6) output projection + residual
    gemm_bf16<1><<<dim3(DD / 128, BNROWS / 128), 512, GSMEMB>>>(atth, attl, woh, wol, b_out, x, nullptr, px2, nullptr, nullptr, BNROWS, DD, DD);
    // 7) FF block
    ln_bf16_kernel<<<BNROWS, 128>>>(px2, fg, fb, ln2h, ln2l);
    gemm_bf16<2><<<dim3(DFF / 128, BNROWS / 128), 512, GSMEMB>>>(ln2h, ln2l, w1h, w1l, b1, nullptr, nullptr, nullptr, h1h, h1l, BNROWS, DFF, DD);
    gemm_bf16<3><<<dim3(DD / 128, BNROWS / 128), 512, GSMEMB>>>(h1h, h1l, w2h, w2l, b2, px2, nmask, out, nullptr, nullptr, BNROWS, DD, DFF);
}

// round 9
// speedup vs baseline: 1.4579x; 1.4579x over previous
#include <cuda_runtime.h>
#include <cuda_bf16.h>
#include <math.h>
#include <float.h>
#include <stdint.h>

// Problem constants
#define BB    32
#define NNODE 256
#define DD    512
#define HH    8
#define EE    1024
#define EDIM  256
#define GDIM  64
#define HDIM  64
#define BNROWS (BB*NNODE)   // 8192
#define DFF   2048

// ---------------- scratch (device globals; no runtime alloc) ----------------
__device__ float g_q  [BNROWS*DD];
__device__ float g_k  [BNROWS*DD];
__device__ float g_v  [BNROWS*DD];
__device__ float g_x2 [BNROWS*DD];
__device__ float g_ebias[BB*EE*HH];
__device__ int   g_wmap[BB*NNODE*NNODE];   // winner edge position per (b,i,j)
__device__ int   g_nbr [BB*NNODE*NNODE];   // compacted neighbor lists
__device__ int   g_cnt [BB*NNODE];

// pre-split bf16 hi/lo activation + weight buffers
__device__ __nv_bfloat16 g_xnh [BNROWS*DD],  g_xnl [BNROWS*DD];
__device__ __nv_bfloat16 g_atth[BNROWS*DD],  g_attl[BNROWS*DD];
__device__ __nv_bfloat16 g_ln2h[BNROWS*DD],  g_ln2l[BNROWS*DD];
__device__ __nv_bfloat16 g_h1h [BNROWS*DFF], g_h1l [BNROWS*DFF];
__device__ __nv_bfloat16 g_wqh[DD*DD], g_wql[DD*DD];
__device__ __nv_bfloat16 g_wkh[DD*DD], g_wkl[DD*DD];
__device__ __nv_bfloat16 g_wvh[DD*DD], g_wvl[DD*DD];
__device__ __nv_bfloat16 g_woh[DD*DD], g_wol[DD*DD];
__device__ __nv_bfloat16 g_w1h[DFF*DD], g_w1l[DFF*DD];
__device__ __nv_bfloat16 g_w2h[DD*DFF], g_w2l[DD*DFF];

// ---------------- fp32 -> bf16 hi/lo split (float4 vectorized) ----------------
__global__ void split4_kernel(const float4* __restrict__ src, __nv_bfloat162* __restrict__ h,
                              __nv_bfloat162* __restrict__ l, int n4) {
    int i = blockIdx.x * 256 + threadIdx.x;
    if (i < n4) {
        float4 v = src[i];
        __nv_bfloat16 h0 = __float2bfloat16_rn(v.x), h1 = __float2bfloat16_rn(v.y);
        __nv_bfloat16 h2 = __float2bfloat16_rn(v.z), h3 = __float2bfloat16_rn(v.w);
        h[2 * i]     = __nv_bfloat162(h0, h1);
        h[2 * i + 1] = __nv_bfloat162(h2, h3);
        l[2 * i]     = __nv_bfloat162(__float2bfloat16_rn(v.x - __bfloat162float(h0)),
                                      __float2bfloat16_rn(v.y - __bfloat162float(h1)));
        l[2 * i + 1] = __nv_bfloat162(__float2bfloat16_rn(v.z - __bfloat162float(h2)),
                                      __float2bfloat16_rn(v.w - __bfloat162float(h3)));
    }
}

// ---------------- LayerNorm -> bf16 hi/lo ----------------
__global__ void ln_bf16_kernel(const float* __restrict__ x, const float* __restrict__ g,
                               const float* __restrict__ b, __nv_bfloat16* __restrict__ yh,
                               __nv_bfloat16* __restrict__ yl) {
    int row = blockIdx.x;
    const float* xr = x + (size_t)row * DD;
    int tid = threadIdx.x; // 128
    float v[4];
    float s = 0.f, s2 = 0.f;
#pragma unroll
    for (int i = 0; i < 4; i++) {
        v[i] = xr[tid + i * 128];
        s += v[i]; s2 += v[i] * v[i];
    }
    __shared__ float rs[4], rs2[4];
    for (int o = 16; o; o >>= 1) {
        s  += __shfl_xor_sync(~0u, s,  o);
        s2 += __shfl_xor_sync(~0u, s2, o);
    }
    int w = tid >> 5;
    if ((tid & 31) == 0) { rs[w] = s; rs2[w] = s2; }
    __syncthreads();
    s  = rs[0] + rs[1] + rs[2] + rs[3];
    s2 = rs2[0] + rs2[1] + rs2[2] + rs2[3];
    float mean = s * (1.f / DD);
    float var  = s2 * (1.f / DD) - mean * mean;
    float r = rsqrtf(var + 1e-5f);
#pragma unroll
    for (int i = 0; i < 4; i++) {
        int c = tid + i * 128;
        float y = (v[i] - mean) * r * g[c] + b[c];
        __nv_bfloat16 hh = __float2bfloat16_rn(y);
        yh[(size_t)row * DD + c] = hh;
        yl[(size_t)row * DD + c] = __float2bfloat16_rn(y - __bfloat162float(hh));
    }
}

// ========== pipelined tensor-core GEMM (R5 winner: 256 thr, 8 warps 4x2, 2-stage) ==========
// C = A(MxK) @ W(NoutxK)^T + bias. EPI: 0=bias->f32, 1=+res->f32, 2=silu->bf16 hi/lo, 3=+res,*rowscale->f32
#define PITCH 40   // bf16 per smem row (32 data + 8 pad) = 80 B
#define GSMEMB 81920

#define CP16(dst, src) \
    asm volatile("cp.async.cg.shared.global [%0], [%1], 16;" :: "r"(dst), "l"(src))

__device__ __forceinline__ void ldsm4(uint32_t a, uint32_t& r0, uint32_t& r1,
                                      uint32_t& r2, uint32_t& r3) {
    asm volatile("ldmatrix.sync.aligned.m8n8.x4.shared.b16 {%0,%1,%2,%3}, [%4];"
                 : "=r"(r0), "=r"(r1), "=r"(r2), "=r"(r3) : "r"(a));
}

__device__ __forceinline__ void mma16816(float (&d)[4], const uint32_t (&a)[4],
                                         const uint32_t* b) {
    asm volatile("mma.sync.aligned.m16n8k16.row.col.f32.bf16.bf16.f32 "
                 "{%0,%1,%2,%3}, {%4,%5,%6,%7}, {%8,%9}, {%0,%1,%2,%3};"
                 : "+f"(d[0]), "+f"(d[1]), "+f"(d[2]), "+f"(d[3])
                 : "r"(a[0]), "r"(a[1]), "r"(a[2]), "r"(a[3]), "r"(b[0]), "r"(b[1]));
}

template<int EPI>
__global__ void __launch_bounds__(256, 1)
gemm_bf16(const __nv_bfloat16* __restrict__ Ah_g, const __nv_bfloat16* __restrict__ Al_g,
          const __nv_bfloat16* __restrict__ Bh_g, const __nv_bfloat16* __restrict__ Bl_g,
          const float* __restrict__ bias, const float* __restrict__ res,
          const float* __restrict__ rowscale, float* __restrict__ C,
          __nv_bfloat16* __restrict__ Ch, __nv_bfloat16* __restrict__ Cl,
          int M, int Nout, int K) {
    extern __shared__ __align__(16) __nv_bfloat16 sm[];
    uint32_t smBase = (uint32_t)__cvta_generic_to_shared(sm);

    int tid = threadIdx.x;               // 256 = 8 warps (4x2)
    int warp = tid >> 5, lane = tid & 31;
    int wm = warp >> 1, wn = warp & 1;
    int bm0 = blockIdx.y * 128, bn0 = blockIdx.x * 128;

    float acc[2][8][4];
#pragma unroll
    for (int i = 0; i < 2; i++)
#pragma unroll
        for (int j = 0; j < 8; j++)
#pragma unroll
            for (int r = 0; r < 4; r++) acc[i][j][r] = 0.f;

    int row0 = tid >> 2, cc0 = (tid & 3);
    int row1 = row0 + 64;

    int a_r  = lane & 15;
    int a_cb = (lane >> 4) << 4;
    uint32_t aOffH = (uint32_t)((wm * 32 + a_r) * (PITCH * 2) + a_cb);
    int b_r  = ((lane >> 4) & 1) * 8 + (lane & 7);
    int b_cb = ((lane >> 3) & 1) << 4;
    uint32_t bOffH = (uint32_t)((wn * 64 + b_r) * (PITCH * 2) + b_cb);

    auto issue_tile = [&](int s, int k0) {
        uint32_t st = smBase + (uint32_t)s * 40960u;
        uint32_t so0 = (uint32_t)((row0 * PITCH + cc0 * 8) * 2);
        uint32_t so1 = (uint32_t)((row1 * PITCH + cc0 * 8) * 2);
        size_t ga0 = (size_t)(bm0 + row0) * K + k0 + cc0 * 8;
        size_t ga1 = (size_t)(bm0 + row1) * K + k0 + cc0 * 8;
        size_t gb0 = (size_t)(bn0 + row0) * K + k0 + cc0 * 8;
        size_t gb1 = (size_t)(bn0 + row1) * K + k0 + cc0 * 8;
        CP16(st + so0,          Ah_g + ga0);
        CP16(st + so1,          Ah_g + ga1);
        CP16(st + 10240 + so0,  Al_g + ga0);
        CP16(st + 10240 + so1,  Al_g + ga1);
        CP16(st + 20480 + so0,  Bh_g + gb0);
        CP16(st + 20480 + so1,  Bh_g + gb1);
        CP16(st + 30720 + so0,  Bl_g + gb0);
        CP16(st + 30720 + so1,  Bl_g + gb1);
    };

    issue_tile(0, 0);
    asm volatile("cp.async.commit_group;");
    issue_tile(1, 32);
    asm volatile("cp.async.commit_group;");

    int ktiles = K >> 5;
#pragma unroll 1
    for (int t = 0; t < ktiles; t++) {
        int s = t & 1;
        asm volatile("cp.async.wait_group 1;");
        __syncthreads();

        uint32_t pAh = smBase + (uint32_t)s * 40960u;
        uint32_t pAl = pAh + 10240u;
        uint32_t pBh = pAh + 20480u;
        uint32_t pBl = pAh + 30720u;
#pragma unroll
        for (int ks = 0; ks < 2; ks++) {
            uint32_t kb = (uint32_t)(ks * 32);
            uint32_t ah[2][4], al[2][4], bh[8][2], bl[8][2];
#pragma unroll
            for (int mi = 0; mi < 2; mi++) {
                uint32_t off = aOffH + (uint32_t)(mi * 16 * PITCH * 2) + kb;
                ldsm4(pAh + off, ah[mi][0], ah[mi][1], ah[mi][2], ah[mi][3]);
                ldsm4(pAl + off, al[mi][0], al[mi][1], al[mi][2], al[mi][3]);
            }
#pragma unroll
            for (int bp = 0; bp < 4; bp++) {
                uint32_t off = bOffH + (uint32_t)(bp * 16 * PITCH * 2) + kb;
                ldsm4(pBh + off, bh[2*bp][0], bh[2*bp][1], bh[2*bp+1][0], bh[2*bp+1][1]);
                ldsm4(pBl + off, bl[2*bp][0], bl[2*bp][1], bl[2*bp+1][0], bl[2*bp+1][1]);
            }
#pragma unroll
            for (int mi = 0; mi < 2; mi++)
#pragma unroll
                for (int ni = 0; ni < 8; ni++) {
                    mma16816(acc[mi][ni], ah[mi], bh[ni]);
                    mma16816(acc[mi][ni], ah[mi], bl[ni]);
                    mma16816(acc[mi][ni], al[mi], bh[ni]);
                }
        }
        __syncthreads();
        int nk = (t + 2) << 5;
        if (nk < K) issue_tile(s, nk);
        asm volatile("cp.async.commit_group;");
    }

    // epilogue
    int qr = lane >> 2, qc = (lane & 3) << 1;
#pragma unroll
    for (int mi = 0; mi < 2; mi++) {
        int m0 = bm0 + wm * 32 + mi * 16 + qr;
#pragma unroll
        for (int ni = 0; ni < 8; ni++) {
            int n = bn0 + wn * 64 + ni * 8 + qc;
            float b0 = bias[n], b1 = bias[n + 1];
#pragma unroll
            for (int rr = 0; rr < 2; rr++) {
                int m = m0 + rr * 8;
                float v0 = acc[mi][ni][rr * 2 + 0] + b0;
                float v1 = acc[mi][ni][rr * 2 + 1] + b1;
                if (EPI == 1 || EPI == 3) {
                    v0 += res[(size_t)m * Nout + n];
                    v1 += res[(size_t)m * Nout + n + 1];
                }
                if (EPI == 2) {
                    v0 = v0 / (1.f + expf(-v0));
                    v1 = v1 / (1.f + expf(-v1));
                    __nv_bfloat16 h0 = __float2bfloat16_rn(v0);
                    __nv_bfloat16 h1 = __float2bfloat16_rn(v1);
                    __nv_bfloat162 hh(h0, h1);
                    __nv_bfloat162 ll(__float2bfloat16_rn(v0 - __bfloat162float(h0)),
                                      __float2bfloat16_rn(v1 - __bfloat162float(h1)));
                    *(__nv_bfloat162*)(Ch + (size_t)m * Nout + n) = hh;
                    *(__nv_bfloat162*)(Cl + (size_t)m * Nout + n) = ll;
                } else {
                    if (EPI == 3) { float rsc = rowscale[m]; v0 *= rsc; v1 *= rsc; }
                    *(float2*)(C + (size_t)m * Nout + n) = make_float2(v0, v1);
                }
            }
        }
    }
}

// ---------------- Edge bias: one warp per (b,e) ----------------
__global__ void edge_bias_kernel(const float* __restrict__ rel, const float* __restrict__ geo,
                                 const float* __restrict__ W_eb, const float* __restrict__ b_eb,
                                 const float* __restrict__ geog, const float* __restrict__ geob,
                                 const float* __restrict__ W_geo, const float* __restrict__ b_geo) {
    int warp = (blockIdx.x * blockDim.x + threadIdx.x) >> 5;
    int lane = threadIdx.x & 31;
    if (warp >= BB * EE) return;
    const float* re = rel + (size_t)warp * EDIM;
    const float* ge = geo + (size_t)warp * GDIM;
    float acc[8] = {0, 0, 0, 0, 0, 0, 0, 0};
#pragma unroll
    for (int it = 0; it < 8; it++) {
        int c = (it << 5) + lane;
        float xv = re[c];
#pragma unroll
        for (int h = 0; h < 8; h++) acc[h] += xv * W_eb[h * EDIM + c];
    }
    float g0 = ge[lane], g1 = ge[lane + 32];
    float s = g0 + g1, s2 = g0 * g0 + g1 * g1;
    for (int o = 16; o; o >>= 1) {
        s  += __shfl_xor_sync(~0u, s,  o);
        s2 += __shfl_xor_sync(~0u, s2, o);
    }
    float mean = s * (1.f / 64.f);
    float var  = s2 * (1.f / 64.f) - mean * mean;
    float r = rsqrtf(var + 1e-5f);
    float n0 = (g0 - mean) * r * geog[lane]      + geob[lane];
    float n1 = (g1 - mean) * r * geog[lane + 32] + geob[lane + 32];
#pragma unroll
    for (int h = 0; h < 8; h++)
        acc[h] += n0 * W_geo[h * GDIM + lane] + n1 * W_geo[h * GDIM + lane + 32];
#pragma unroll
    for (int h = 0; h < 8; h++) {
        float v = acc[h];
        for (int o = 16; o; o >>= 1) v += __shfl_xor_sync(~0u, v, o);
        if (lane == h) g_ebias[(size_t)warp * HH + h] = v + b_eb[h] + b_geo[h];
    }
}

// ---------------- winner map + scatter ----------------
__global__ void wmap_init_kernel() {
    int idx = blockIdx.x * 256 + threadIdx.x;
    g_wmap[idx] = -1;
}

__global__ void wmap_scatter_kernel(const int* __restrict__ edges, const float* __restrict__ emask) {
    int t = blockIdx.x * 256 + threadIdx.x;
    if (t >= BB * EE) return;
    int b = t >> 10, e = t & 1023;
    if (emask[t] > 0.5f) {
        int s = min(max(edges[2 * t], 0), NNODE - 1);
        int d = min(max(edges[2 * t + 1], 0), NNODE - 1);
        atomicMax(&g_wmap[b * 65536 + s * 256 + d], e);
        atomicMax(&g_wmap[b * 65536 + d * 256 + s], e + EE);
    }
}

// ---------------- neighbor-list compaction: one warp per (b,i) ----------------
__global__ void nbr_kernel(const float* __restrict__ nmask) {
    int gw = (blockIdx.x * blockDim.x + threadIdx.x) >> 5;
    int lane = threadIdx.x & 31;
    if (gw >= BB * NNODE) return;
    int b = gw >> 8, i = gw & 255;
    if (nmask[gw] == 0.f) {
        if (lane == 0) g_cnt[gw] = 0;
        return;
    }
    const int* wrow = g_wmap + (size_t)gw * 256;
    int* nrow = g_nbr + (size_t)gw * 256;
    int base = 0;
#pragma unroll
    for (int c = 0; c < 8; c++) {
        int j = c * 32 + lane;
        int w = wrow[j];
        bool valid = ((w >= 0) || (j == i)) && (nmask[b * 256 + j] != 0.f);
        unsigned m = __ballot_sync(~0u, valid);
        if (valid) {
            int pos = base + __popc(m & ((1u << lane) - 1));
            nrow[pos] = ((w + 1) << 8) | j;
        }
        base += __popc(m);
    }
    if (lane == 0) g_cnt[gw] = base;
}

// ---------------- sparse attention: block per (b,i), warp per head ----------------
__global__ void __launch_bounds__(256)
attn_sparse_kernel() {
    __shared__ float sc[HH][NNODE];   // scores/probs per head
    __shared__ float qs[HH][64];

    int bi = blockIdx.x;              // 0..8191 = b*256 + i
    int b = bi >> 8;
    int tid = threadIdx.x, h = tid >> 5, lane = tid & 31;
    size_t orow = (size_t)bi * DD + h * HDIM;

    int cnt = g_cnt[bi];
    if (cnt == 0) {
        __nv_bfloat162 z(__float2bfloat16_rn(0.f), __float2bfloat16_rn(0.f));
        int d0 = lane << 1;
        *(__nv_bfloat162*)&g_atth[orow + d0] = z;
        *(__nv_bfloat162*)&g_attl[orow + d0] = z;
        return;
    }

    qs[h][lane]      = g_q[orow + lane];
    qs[h][lane + 32] = g_q[orow + lane + 32];
    __syncwarp();

    const int* nrow = g_nbr + (size_t)bi * 256;
    const float* qh = qs[h];

    // pass 1: scores + running max (lanes parallel over neighbor slots)
    float mx = -FLT_MAX;
    for (int c0 = 0; c0 < cnt; c0 += 32) {
        int idx = c0 + lane;
        float s = -FLT_MAX;
        if (idx < cnt) {
            int packed = nrow[idx];
            int j = packed & 255;
            int w = (packed >> 8) - 1;
            const float* kr = g_k + (size_t)(b * NNODE + j) * DD + h * HDIM;
            float a = 0.f;
#pragma unroll
            for (int d4 = 0; d4 < 16; d4++) {
                float4 kv = *(const float4*)(kr + d4 * 4);
                a += kv.x * qh[d4 * 4] + kv.y * qh[d4 * 4 + 1]
                   + kv.z * qh[d4 * 4 + 2] + kv.w * qh[d4 * 4 + 3];
            }
            float bias = 0.f;
            if (w >= 0) {
                int e = (w >= EE) ? w - EE : w;
                bias = g_ebias[((size_t)b * EE + e) * HH + h];
            }
            s = a * 0.125f + bias;
            sc[h][idx] = s;
        }
        mx = fmaxf(mx, s);
    }
    for (int o = 16; o; o >>= 1) mx = fmaxf(mx, __shfl_xor_sync(~0u, mx, o));

    // pass 2: exp + sum
    float sum = 0.f;
    for (int c0 = 0; c0 < cnt; c0 += 32) {
        int idx = c0 + lane;
        if (idx < cnt) {
            float p = expf(sc[h][idx] - mx);
            sc[h][idx] = p;
            sum += p;
        }
    }
    for (int o = 16; o; o >>= 1) sum += __shfl_xor_sync(~0u, sum, o);
    float inv = 1.f / sum;
    __syncwarp();

    // pass 3: PV (lanes parallel over d; serial over neighbors)
    int d0 = lane << 1;
    float o0 = 0.f, o1 = 0.f;
    for (int idx = 0; idx < cnt; idx++) {
        int j = nrow[idx] & 255;
        float p = sc[h][idx];
        const float* vr = g_v + (size_t)(b * NNODE + j) * DD + h * HDIM;
        float2 vv = *(const float2*)(vr + d0);
        o0 += p * vv.x;
        o1 += p * vv.y;
    }
    o0 *= inv; o1 *= inv;
    __nv_bfloat16 h0 = __float2bfloat16_rn(o0);
    __nv_bfloat16 h1 = __float2bfloat16_rn(o1);
    *(__nv_bfloat162*)&g_atth[orow + d0] = __nv_bfloat162(h0, h1);
    *(__nv_bfloat162*)&g_attl[orow + d0] =
        __nv_bfloat162(__float2bfloat16_rn(o0 - __bfloat162float(h0)),
                       __float2bfloat16_rn(o1 - __bfloat162float(h1)));
}

// ---------------- host launcher ----------------
extern "C" void kernel_launch(void* const* d_in, const int* in_sizes, int n_in,
                              void* d_out, int out_size) {
    const float* x     = (const float*)d_in[0];
    const float* nmask = (const float*)d_in[1];
    const int*   edges = (const int*)  d_in[2];
    const float* emask = (const float*)d_in[3];
    const float* rel   = (const float*)d_in[4];
    const float* geo   = (const float*)d_in[5];
    const float* Wq = (const float*)d_in[6];  const float* bq = (const float*)d_in[7];
    const float* Wk = (const float*)d_in[8];  const float* bk = (const float*)d_in[9];
    const float* Wv = (const float*)d_in[10]; const float* bv = (const float*)d_in[11];
    const float* W_eb = (const float*)d_in[12]; const float* b_eb = (const float*)d_in[13];
    const float* geog = (const float*)d_in[14]; const float* geob = (const float*)d_in[15];
    const float* W_geo = (const float*)d_in[16]; const float* b_geo = (const float*)d_in[17];
    const float* W_out = (const float*)d_in[18]; const float* b_out = (const float*)d_in[19];
    const float* ng = (const float*)d_in[20]; const float* nb = (const float*)d_in[21];
    const float* fg = (const float*)d_in[22]; const float* fb = (const float*)d_in[23];
    const float* W1 = (const float*)d_in[24]; const float* b1 = (const float*)d_in[25];
    const float* W2 = (const float*)d_in[26]; const float* b2 = (const float*)d_in[27];
    float* out = (float*)d_out;

    float *pq, *pk, *pv, *px2;
    cudaGetSymbolAddress((void**)&pq,  g_q);
    cudaGetSymbolAddress((void**)&pk,  g_k);
    cudaGetSymbolAddress((void**)&pv,  g_v);
    cudaGetSymbolAddress((void**)&px2, g_x2);
    __nv_bfloat16 *xnh, *xnl, *atth, *attl, *ln2h, *ln2l, *h1h, *h1l;
    __nv_bfloat16 *wqh, *wql, *wkh, *wkl, *wvh, *wvl, *woh, *wol, *w1h, *w1l, *w2h, *w2l;
    cudaGetSymbolAddress((void**)&xnh,  g_xnh);  cudaGetSymbolAddress((void**)&xnl,  g_xnl);
    cudaGetSymbolAddress((void**)&atth, g_atth); cudaGetSymbolAddress((void**)&attl, g_attl);
    cudaGetSymbolAddress((void**)&ln2h, g_ln2h); cudaGetSymbolAddress((void**)&ln2l, g_ln2l);
    cudaGetSymbolAddress((void**)&h1h,  g_h1h);  cudaGetSymbolAddress((void**)&h1l,  g_h1l);
    cudaGetSymbolAddress((void**)&wqh, g_wqh);   cudaGetSymbolAddress((void**)&wql, g_wql);
    cudaGetSymbolAddress((void**)&wkh, g_wkh);   cudaGetSymbolAddress((void**)&wkl, g_wkl);
    cudaGetSymbolAddress((void**)&wvh, g_wvh);   cudaGetSymbolAddress((void**)&wvl, g_wvl);
    cudaGetSymbolAddress((void**)&woh, g_woh);   cudaGetSymbolAddress((void**)&wol, g_wol);
    cudaGetSymbolAddress((void**)&w1h, g_w1h);   cudaGetSymbolAddress((void**)&w1l, g_w1l);
    cudaGetSymbolAddress((void**)&w2h, g_w2h);   cudaGetSymbolAddress((void**)&w2l, g_w2l);

    cudaFuncSetAttribute(gemm_bf16<0>, cudaFuncAttributeMaxDynamicSharedMemorySize, GSMEMB);
    cudaFuncSetAttribute(gemm_bf16<1>, cudaFuncAttributeMaxDynamicSharedMemorySize, GSMEMB);
    cudaFuncSetAttribute(gemm_bf16<2>, cudaFuncAttributeMaxDynamicSharedMemorySize, GSMEMB);
    cudaFuncSetAttribute(gemm_bf16<3>, cudaFuncAttributeMaxDynamicSharedMemorySize, GSMEMB);

    // 0) weight splits (vectorized)
    split4_kernel<<<DD * DD / 1024, 256>>>((const float4*)Wq,   (__nv_bfloat162*)wqh, (__nv_bfloat162*)wql, DD * DD / 4);
    split4_kernel<<<DD * DD / 1024, 256>>>((const float4*)Wk,   (__nv_bfloat162*)wkh, (__nv_bfloat162*)wkl, DD * DD / 4);
    split4_kernel<<<DD * DD / 1024, 256>>>((const float4*)Wv,   (__nv_bfloat162*)wvh, (__nv_bfloat162*)wvl, DD * DD / 4);
    split4_kernel<<<DD * DD / 1024, 256>>>((const float4*)W_out,(__nv_bfloat162*)woh, (__nv_bfloat162*)wol, DD * DD / 4);
    split4_kernel<<<DFF * DD / 1024, 256>>>((const float4*)W1,  (__nv_bfloat162*)w1h, (__nv_bfloat162*)w1l, DFF * DD / 4);
    split4_kernel<<<DD * DFF / 1024, 256>>>((const float4*)W2,  (__nv_bfloat162*)w2h, (__nv_bfloat162*)w2l, DD * DFF / 4);
    // 1) pre-LN -> bf16 split
    ln_bf16_kernel<<<BNROWS, 128>>>(x, ng, nb, xnh, xnl);
    // 2) Q,K,V projections
    gemm_bf16<0><<<dim3(DD / 128, BNROWS / 128), 256, GSMEMB>>>(xnh, xnl, wqh, wql, bq, nullptr, nullptr, pq, nullptr, nullptr, BNROWS, DD, DD);
    gemm_bf16<0><<<dim3(DD / 128, BNROWS / 128), 256, GSMEMB>>>(xnh, xnl, wkh, wkl, bk, nullptr, nullptr, pk, nullptr, nullptr, BNROWS, DD, DD);
    gemm_bf16<0><<<dim3(DD / 128, BNROWS / 128), 256, GSMEMB>>>(xnh, xnl, wvh, wvl, bv, nullptr, nullptr, pv, nullptr, nullptr, BNROWS, DD, DD);
    // 3) per-edge bias
    edge_bias_kernel<<<(BB * EE) / 8, 256>>>(rel, geo, W_eb, b_eb, geog, geob, W_geo, b_geo);
    // 4) winner map + neighbor compaction
    wmap_init_kernel<<<(BB * NNODE * NNODE) / 256, 256>>>();
    wmap_scatter_kernel<<<(BB * EE) / 256, 256>>>(edges, emask);
    nbr_kernel<<<(BB * NNODE) / 8, 256>>>(nmask);
    // 5) sparse attention
    attn_sparse_kernel<<<BB * NNODE, 256>>>();
    // 6) output projection + residual
    gemm_bf16<1><<<dim3(DD / 128, BNROWS / 128), 256, GSMEMB>>>(atth, attl, woh, wol, b_out, x, nullptr, px2, nullptr, nullptr, BNROWS, DD, DD);
    // 7) FF block
    ln_bf16_kernel<<<BNROWS, 128>>>(px2, fg, fb, ln2h, ln2l);
    gemm_bf16<2><<<dim3(DFF / 128, BNROWS / 128), 256, GSMEMB>>>(ln2h, ln2l, w1h, w1l, b1, nullptr, nullptr, nullptr, h1h, h1l, BNROWS, DFF, DD);
    gemm_bf16<3><<<dim3(DD / 128, BNROWS / 128), 256, GSMEMB>>>(h1h, h1l, w2h, w2l, b2, px2, nmask, out, nullptr, nullptr, BNROWS, DD, DFF);
}

// round 10
// speedup vs baseline: 1.6550x; 1.1352x over previous
#include <cuda_runtime.h>
#include <cuda_bf16.h>
#include <math.h>
#include <float.h>
#include <stdint.h>

// Problem constants
#define BB    32
#define NNODE 256
#define DD    512
#define HH    8
#define EE    1024
#define EDIM  256
#define GDIM  64
#define HDIM  64
#define BNROWS (BB*NNODE)   // 8192
#define DFF   2048

// ---------------- scratch (device globals; no runtime alloc) ----------------
__device__ float g_q  [BNROWS*DD];
__device__ float g_k  [BNROWS*DD];
__device__ float g_v  [BNROWS*DD];
__device__ float g_x2 [BNROWS*DD];
__device__ float g_ebias[BB*EE*HH];
__device__ int   g_wmap[BB*NNODE*NNODE];   // winner edge position per (b,i,j)
__device__ int   g_nbr [BB*NNODE*NNODE];   // compacted neighbor lists
__device__ int   g_cnt [BB*NNODE];

// pre-split bf16 hi/lo activation + weight buffers
__device__ __nv_bfloat16 g_xnh [BNROWS*DD],  g_xnl [BNROWS*DD];
__device__ __nv_bfloat16 g_atth[BNROWS*DD],  g_attl[BNROWS*DD];
__device__ __nv_bfloat16 g_ln2h[BNROWS*DD],  g_ln2l[BNROWS*DD];
__device__ __nv_bfloat16 g_h1h [BNROWS*DFF], g_h1l [BNROWS*DFF];
__device__ __nv_bfloat16 g_wqh[DD*DD], g_wql[DD*DD];
__device__ __nv_bfloat16 g_wkh[DD*DD], g_wkl[DD*DD];
__device__ __nv_bfloat16 g_wvh[DD*DD], g_wvl[DD*DD];
__device__ __nv_bfloat16 g_woh[DD*DD], g_wol[DD*DD];
__device__ __nv_bfloat16 g_w1h[DFF*DD], g_w1l[DFF*DD];
__device__ __nv_bfloat16 g_w2h[DD*DFF], g_w2l[DD*DFF];

// ---------------- fp32 -> bf16 hi/lo split (float4 vectorized) ----------------
__global__ void split4_kernel(const float4* __restrict__ src, __nv_bfloat162* __restrict__ h,
                              __nv_bfloat162* __restrict__ l, int n4) {
    int i = blockIdx.x * 256 + threadIdx.x;
    if (i < n4) {
        float4 v = src[i];
        __nv_bfloat16 h0 = __float2bfloat16_rn(v.x), h1 = __float2bfloat16_rn(v.y);
        __nv_bfloat16 h2 = __float2bfloat16_rn(v.z), h3 = __float2bfloat16_rn(v.w);
        h[2 * i]     = __nv_bfloat162(h0, h1);
        h[2 * i + 1] = __nv_bfloat162(h2, h3);
        l[2 * i]     = __nv_bfloat162(__float2bfloat16_rn(v.x - __bfloat162float(h0)),
                                      __float2bfloat16_rn(v.y - __bfloat162float(h1)));
        l[2 * i + 1] = __nv_bfloat162(__float2bfloat16_rn(v.z - __bfloat162float(h2)),
                                      __float2bfloat16_rn(v.w - __bfloat162float(h3)));
    }
}

// ---------------- LayerNorm -> bf16 hi/lo ----------------
__global__ void ln_bf16_kernel(const float* __restrict__ x, const float* __restrict__ g,
                               const float* __restrict__ b, __nv_bfloat16* __restrict__ yh,
                               __nv_bfloat16* __restrict__ yl) {
    int row = blockIdx.x;
    const float* xr = x + (size_t)row * DD;
    int tid = threadIdx.x; // 128
    float v[4];
    float s = 0.f, s2 = 0.f;
#pragma unroll
    for (int i = 0; i < 4; i++) {
        v[i] = xr[tid + i * 128];
        s += v[i]; s2 += v[i] * v[i];
    }
    __shared__ float rs[4], rs2[4];
    for (int o = 16; o; o >>= 1) {
        s  += __shfl_xor_sync(~0u, s,  o);
        s2 += __shfl_xor_sync(~0u, s2, o);
    }
    int w = tid >> 5;
    if ((tid & 31) == 0) { rs[w] = s; rs2[w] = s2; }
    __syncthreads();
    s  = rs[0] + rs[1] + rs[2] + rs[3];
    s2 = rs2[0] + rs2[1] + rs2[2] + rs2[3];
    float mean = s * (1.f / DD);
    float var  = s2 * (1.f / DD) - mean * mean;
    float r = rsqrtf(var + 1e-5f);
#pragma unroll
    for (int i = 0; i < 4; i++) {
        int c = tid + i * 128;
        float y = (v[i] - mean) * r * g[c] + b[c];
        __nv_bfloat16 hh = __float2bfloat16_rn(y);
        yh[(size_t)row * DD + c] = hh;
        yl[(size_t)row * DD + c] = __float2bfloat16_rn(y - __bfloat162float(hh));
    }
}

// ========== pipelined tensor-core GEMM: 256 thr, 8 warps 4x2, 2-stage, 2 CTA/SM ==========
// C = A(MxK) @ W(NoutxK)^T + bias. EPI: 0=bias->f32, 1=+res->f32, 2=silu->bf16 hi/lo, 3=+res,*rowscale->f32
#define PITCH 40   // bf16 per smem row (32 data + 8 pad) = 80 B
#define GSMEMB 81920

#define CP16(dst, src) \
    asm volatile("cp.async.cg.shared.global [%0], [%1], 16;" :: "r"(dst), "l"(src))

__device__ __forceinline__ void ldsm4(uint32_t a, uint32_t& r0, uint32_t& r1,
                                      uint32_t& r2, uint32_t& r3) {
    asm volatile("ldmatrix.sync.aligned.m8n8.x4.shared.b16 {%0,%1,%2,%3}, [%4];"
                 : "=r"(r0), "=r"(r1), "=r"(r2), "=r"(r3) : "r"(a));
}

__device__ __forceinline__ void mma16816(float (&d)[4], const uint32_t (&a)[4],
                                         const uint32_t* b) {
    asm volatile("mma.sync.aligned.m16n8k16.row.col.f32.bf16.bf16.f32 "
                 "{%0,%1,%2,%3}, {%4,%5,%6,%7}, {%8,%9}, {%0,%1,%2,%3};"
                 : "+f"(d[0]), "+f"(d[1]), "+f"(d[2]), "+f"(d[3])
                 : "r"(a[0]), "r"(a[1]), "r"(a[2]), "r"(a[3]), "r"(b[0]), "r"(b[1]));
}

template<int EPI>
__global__ void __launch_bounds__(256, 2)
gemm_bf16(const __nv_bfloat16* __restrict__ Ah_g, const __nv_bfloat16* __restrict__ Al_g,
          const __nv_bfloat16* __restrict__ Bh_g, const __nv_bfloat16* __restrict__ Bl_g,
          const float* __restrict__ bias, const float* __restrict__ res,
          const float* __restrict__ rowscale, float* __restrict__ C,
          __nv_bfloat16* __restrict__ Ch, __nv_bfloat16* __restrict__ Cl,
          int M, int Nout, int K) {
    extern __shared__ __align__(16) __nv_bfloat16 sm[];
    uint32_t smBase = (uint32_t)__cvta_generic_to_shared(sm);

    int tid = threadIdx.x;               // 256 = 8 warps (4x2)
    int warp = tid >> 5, lane = tid & 31;
    int wm = warp >> 1, wn = warp & 1;
    int bm0 = blockIdx.y * 128, bn0 = blockIdx.x * 128;

    float acc[2][8][4];
#pragma unroll
    for (int i = 0; i < 2; i++)
#pragma unroll
        for (int j = 0; j < 8; j++)
#pragma unroll
            for (int r = 0; r < 4; r++) acc[i][j][r] = 0.f;

    int row0 = tid >> 2, cc0 = (tid & 3);
    int row1 = row0 + 64;

    int a_r  = lane & 15;
    int a_cb = (lane >> 4) << 4;
    uint32_t aOffH = (uint32_t)((wm * 32 + a_r) * (PITCH * 2) + a_cb);
    int b_r  = ((lane >> 4) & 1) * 8 + (lane & 7);
    int b_cb = ((lane >> 3) & 1) << 4;
    uint32_t bOffH = (uint32_t)((wn * 64 + b_r) * (PITCH * 2) + b_cb);

    auto issue_tile = [&](int s, int k0) {
        uint32_t st = smBase + (uint32_t)s * 40960u;
        uint32_t so0 = (uint32_t)((row0 * PITCH + cc0 * 8) * 2);
        uint32_t so1 = (uint32_t)((row1 * PITCH + cc0 * 8) * 2);
        size_t ga0 = (size_t)(bm0 + row0) * K + k0 + cc0 * 8;
        size_t ga1 = (size_t)(bm0 + row1) * K + k0 + cc0 * 8;
        size_t gb0 = (size_t)(bn0 + row0) * K + k0 + cc0 * 8;
        size_t gb1 = (size_t)(bn0 + row1) * K + k0 + cc0 * 8;
        CP16(st + so0,          Ah_g + ga0);
        CP16(st + so1,          Ah_g + ga1);
        CP16(st + 10240 + so0,  Al_g + ga0);
        CP16(st + 10240 + so1,  Al_g + ga1);
        CP16(st + 20480 + so0,  Bh_g + gb0);
        CP16(st + 20480 + so1,  Bh_g + gb1);
        CP16(st + 30720 + so0,  Bl_g + gb0);
        CP16(st + 30720 + so1,  Bl_g + gb1);
    };

    issue_tile(0, 0);
    asm volatile("cp.async.commit_group;");
    issue_tile(1, 32);
    asm volatile("cp.async.commit_group;");

    int ktiles = K >> 5;
#pragma unroll 1
    for (int t = 0; t < ktiles; t++) {
        int s = t & 1;
        asm volatile("cp.async.wait_group 1;");
        __syncthreads();

        uint32_t pAh = smBase + (uint32_t)s * 40960u;
        uint32_t pAl = pAh + 10240u;
        uint32_t pBh = pAh + 20480u;
        uint32_t pBl = pAh + 30720u;
#pragma unroll
        for (int ks = 0; ks < 2; ks++) {
            uint32_t kb = (uint32_t)(ks * 32);
            uint32_t ah[2][4], al[2][4];
#pragma unroll
            for (int mi = 0; mi < 2; mi++) {
                uint32_t off = aOffH + (uint32_t)(mi * 16 * PITCH * 2) + kb;
                ldsm4(pAh + off, ah[mi][0], ah[mi][1], ah[mi][2], ah[mi][3]);
                ldsm4(pAl + off, al[mi][0], al[mi][1], al[mi][2], al[mi][3]);
            }
            // per-bp B fragments keep live register set small (2 CTA/SM fit)
#pragma unroll
            for (int bp = 0; bp < 4; bp++) {
                uint32_t off = bOffH + (uint32_t)(bp * 16 * PITCH * 2) + kb;
                uint32_t bh[2][2], bl[2][2];
                ldsm4(pBh + off, bh[0][0], bh[0][1], bh[1][0], bh[1][1]);
                ldsm4(pBl + off, bl[0][0], bl[0][1], bl[1][0], bl[1][1]);
#pragma unroll
                for (int mi = 0; mi < 2; mi++)
#pragma unroll
                    for (int q = 0; q < 2; q++) {
                        int ni = 2 * bp + q;
                        mma16816(acc[mi][ni], ah[mi], bh[q]);
                        mma16816(acc[mi][ni], ah[mi], bl[q]);
                        mma16816(acc[mi][ni], al[mi], bh[q]);
                    }
            }
        }
        __syncthreads();
        int nk = (t + 2) << 5;
        if (nk < K) issue_tile(s, nk);
        asm volatile("cp.async.commit_group;");
    }

    // epilogue
    int qr = lane >> 2, qc = (lane & 3) << 1;
#pragma unroll
    for (int mi = 0; mi < 2; mi++) {
        int m0 = bm0 + wm * 32 + mi * 16 + qr;
#pragma unroll
        for (int ni = 0; ni < 8; ni++) {
            int n = bn0 + wn * 64 + ni * 8 + qc;
            float b0 = bias[n], b1 = bias[n + 1];
#pragma unroll
            for (int rr = 0; rr < 2; rr++) {
                int m = m0 + rr * 8;
                float v0 = acc[mi][ni][rr * 2 + 0] + b0;
                float v1 = acc[mi][ni][rr * 2 + 1] + b1;
                if (EPI == 1 || EPI == 3) {
                    v0 += res[(size_t)m * Nout + n];
                    v1 += res[(size_t)m * Nout + n + 1];
                }
                if (EPI == 2) {
                    v0 = v0 / (1.f + expf(-v0));
                    v1 = v1 / (1.f + expf(-v1));
                    __nv_bfloat16 h0 = __float2bfloat16_rn(v0);
                    __nv_bfloat16 h1 = __float2bfloat16_rn(v1);
                    __nv_bfloat162 hh(h0, h1);
                    __nv_bfloat162 ll(__float2bfloat16_rn(v0 - __bfloat162float(h0)),
                                      __float2bfloat16_rn(v1 - __bfloat162float(h1)));
                    *(__nv_bfloat162*)(Ch + (size_t)m * Nout + n) = hh;
                    *(__nv_bfloat162*)(Cl + (size_t)m * Nout + n) = ll;
                } else {
                    if (EPI == 3) { float rsc = rowscale[m]; v0 *= rsc; v1 *= rsc; }
                    *(float2*)(C + (size_t)m * Nout + n) = make_float2(v0, v1);
                }
            }
        }
    }
}

// ---------------- Edge bias: one warp per (b,e) ----------------
__global__ void edge_bias_kernel(const float* __restrict__ rel, const float* __restrict__ geo,
                                 const float* __restrict__ W_eb, const float* __restrict__ b_eb,
                                 const float* __restrict__ geog, const float* __restrict__ geob,
                                 const float* __restrict__ W_geo, const float* __restrict__ b_geo) {
    int warp = (blockIdx.x * blockDim.x + threadIdx.x) >> 5;
    int lane = threadIdx.x & 31;
    if (warp >= BB * EE) return;
    const float* re = rel + (size_t)warp * EDIM;
    const float* ge = geo + (size_t)warp * GDIM;
    float acc[8] = {0, 0, 0, 0, 0, 0, 0, 0};
#pragma unroll
    for (int it = 0; it < 8; it++) {
        int c = (it << 5) + lane;
        float xv = re[c];
#pragma unroll
        for (int h = 0; h < 8; h++) acc[h] += xv * W_eb[h * EDIM + c];
    }
    float g0 = ge[lane], g1 = ge[lane + 32];
    float s = g0 + g1, s2 = g0 * g0 + g1 * g1;
    for (int o = 16; o; o >>= 1) {
        s  += __shfl_xor_sync(~0u, s,  o);
        s2 += __shfl_xor_sync(~0u, s2, o);
    }
    float mean = s * (1.f / 64.f);
    float var  = s2 * (1.f / 64.f) - mean * mean;
    float r = rsqrtf(var + 1e-5f);
    float n0 = (g0 - mean) * r * geog[lane]      + geob[lane];
    float n1 = (g1 - mean) * r * geog[lane + 32] + geob[lane + 32];
#pragma unroll
    for (int h = 0; h < 8; h++)
        acc[h] += n0 * W_geo[h * GDIM + lane] + n1 * W_geo[h * GDIM + lane + 32];
#pragma unroll
    for (int h = 0; h < 8; h++) {
        float v = acc[h];
        for (int o = 16; o; o >>= 1) v += __shfl_xor_sync(~0u, v, o);
        if (lane == h) g_ebias[(size_t)warp * HH + h] = v + b_eb[h] + b_geo[h];
    }
}

// ---------------- winner map + scatter ----------------
__global__ void wmap_init_kernel() {
    int idx = blockIdx.x * 256 + threadIdx.x;
    g_wmap[idx] = -1;
}

__global__ void wmap_scatter_kernel(const int* __restrict__ edges, const float* __restrict__ emask) {
    int t = blockIdx.x * 256 + threadIdx.x;
    if (t >= BB * EE) return;
    int b = t >> 10, e = t & 1023;
    if (emask[t] > 0.5f) {
        int s = min(max(edges[2 * t], 0), NNODE - 1);
        int d = min(max(edges[2 * t + 1], 0), NNODE - 1);
        atomicMax(&g_wmap[b * 65536 + s * 256 + d], e);
        atomicMax(&g_wmap[b * 65536 + d * 256 + s], e + EE);
    }
}

// ---------------- neighbor-list compaction: one warp per (b,i) ----------------
__global__ void nbr_kernel(const float* __restrict__ nmask) {
    int gw = (blockIdx.x * blockDim.x + threadIdx.x) >> 5;
    int lane = threadIdx.x & 31;
    if (gw >= BB * NNODE) return;
    int b = gw >> 8, i = gw & 255;
    if (nmask[gw] == 0.f) {
        if (lane == 0) g_cnt[gw] = 0;
        return;
    }
    const int* wrow = g_wmap + (size_t)gw * 256;
    int* nrow = g_nbr + (size_t)gw * 256;
    int base = 0;
#pragma unroll
    for (int c = 0; c < 8; c++) {
        int j = c * 32 + lane;
        int w = wrow[j];
        bool valid = ((w >= 0) || (j == i)) && (nmask[b * 256 + j] != 0.f);
        unsigned m = __ballot_sync(~0u, valid);
        if (valid) {
            int pos = base + __popc(m & ((1u << lane) - 1));
            nrow[pos] = ((w + 1) << 8) | j;
        }
        base += __popc(m);
    }
    if (lane == 0) g_cnt[gw] = base;
}

// ---------------- sparse attention: block per (b,i), warp per head ----------------
__global__ void __launch_bounds__(256)
attn_sparse_kernel() {
    __shared__ float sc[HH][NNODE];
    __shared__ float qs[HH][64];

    int bi = blockIdx.x;
    int b = bi >> 8;
    int tid = threadIdx.x, h = tid >> 5, lane = tid & 31;
    size_t orow = (size_t)bi * DD + h * HDIM;

    int cnt = g_cnt[bi];
    if (cnt == 0) {
        __nv_bfloat162 z(__float2bfloat16_rn(0.f), __float2bfloat16_rn(0.f));
        int d0 = lane << 1;
        *(__nv_bfloat162*)&g_atth[orow + d0] = z;
        *(__nv_bfloat162*)&g_attl[orow + d0] = z;
        return;
    }

    qs[h][lane]      = g_q[orow + lane];
    qs[h][lane + 32] = g_q[orow + lane + 32];
    __syncwarp();

    const int* nrow = g_nbr + (size_t)bi * 256;
    const float* qh = qs[h];

    float mx = -FLT_MAX;
    for (int c0 = 0; c0 < cnt; c0 += 32) {
        int idx = c0 + lane;
        float s = -FLT_MAX;
        if (idx < cnt) {
            int packed = nrow[idx];
            int j = packed & 255;
            int w = (packed >> 8) - 1;
            const float* kr = g_k + (size_t)(b * NNODE + j) * DD + h * HDIM;
            float a = 0.f;
#pragma unroll
            for (int d4 = 0; d4 < 16; d4++) {
                float4 kv = *(const float4*)(kr + d4 * 4);
                a += kv.x * qh[d4 * 4] + kv.y * qh[d4 * 4 + 1]
                   + kv.z * qh[d4 * 4 + 2] + kv.w * qh[d4 * 4 + 3];
            }
            float bias = 0.f;
            if (w >= 0) {
                int e = (w >= EE) ? w - EE : w;
                bias = g_ebias[((size_t)b * EE + e) * HH + h];
            }
            s = a * 0.125f + bias;
            sc[h][idx] = s;
        }
        mx = fmaxf(mx, s);
    }
    for (int o = 16; o; o >>= 1) mx = fmaxf(mx, __shfl_xor_sync(~0u, mx, o));

    float sum = 0.f;
    for (int c0 = 0; c0 < cnt; c0 += 32) {
        int idx = c0 + lane;
        if (idx < cnt) {
            float p = expf(sc[h][idx] - mx);
            sc[h][idx] = p;
            sum += p;
        }
    }
    for (int o = 16; o; o >>= 1) sum += __shfl_xor_sync(~0u, sum, o);
    float inv = 1.f / sum;
    __syncwarp();

    int d0 = lane << 1;
    float o0 = 0.f, o1 = 0.f;
    for (int idx = 0; idx < cnt; idx++) {
        int j = nrow[idx] & 255;
        float p = sc[h][idx];
        const float* vr = g_v + (size_t)(b * NNODE + j) * DD + h * HDIM;
        float2 vv = *(const float2*)(vr + d0);
        o0 += p * vv.x;
        o1 += p * vv.y;
    }
    o0 *= inv; o1 *= inv;
    __nv_bfloat16 h0 = __float2bfloat16_rn(o0);
    __nv_bfloat16 h1 = __float2bfloat16_rn(o1);
    *(__nv_bfloat162*)&g_atth[orow + d0] = __nv_bfloat162(h0, h1);
    *(__nv_bfloat162*)&g_attl[orow + d0] =
        __nv_bfloat162(__float2bfloat16_rn(o0 - __bfloat162float(h0)),
                       __float2bfloat16_rn(o1 - __bfloat162float(h1)));
}

// ---------------- host launcher ----------------
extern "C" void kernel_launch(void* const* d_in, const int* in_sizes, int n_in,
                              void* d_out, int out_size) {
    const float* x     = (const float*)d_in[0];
    const float* nmask = (const float*)d_in[1];
    const int*   edges = (const int*)  d_in[2];
    const float* emask = (const float*)d_in[3];
    const float* rel   = (const float*)d_in[4];
    const float* geo   = (const float*)d_in[5];
    const float* Wq = (const float*)d_in[6];  const float* bq = (const float*)d_in[7];
    const float* Wk = (const float*)d_in[8];  const float* bk = (const float*)d_in[9];
    const float* Wv = (const float*)d_in[10]; const float* bv = (const float*)d_in[11];
    const float* W_eb = (const float*)d_in[12]; const float* b_eb = (const float*)d_in[13];
    const float* geog = (const float*)d_in[14]; const float* geob = (const float*)d_in[15];
    const float* W_geo = (const float*)d_in[16]; const float* b_geo = (const float*)d_in[17];
    const float* W_out = (const float*)d_in[18]; const float* b_out = (const float*)d_in[19];
    const float* ng = (const float*)d_in[20]; const float* nb = (const float*)d_in[21];
    const float* fg = (const float*)d_in[22]; const float* fb = (const float*)d_in[23];
    const float* W1 = (const float*)d_in[24]; const float* b1 = (const float*)d_in[25];
    const float* W2 = (const float*)d_in[26]; const float* b2 = (const float*)d_in[27];
    float* out = (float*)d_out;

    float *pq, *pk, *pv, *px2;
    cudaGetSymbolAddress((void**)&pq,  g_q);
    cudaGetSymbolAddress((void**)&pk,  g_k);
    cudaGetSymbolAddress((void**)&pv,  g_v);
    cudaGetSymbolAddress((void**)&px2, g_x2);
    __nv_bfloat16 *xnh, *xnl, *atth, *attl, *ln2h, *ln2l, *h1h, *h1l;
    __nv_bfloat16 *wqh, *wql, *wkh, *wkl, *wvh, *wvl, *woh, *wol, *w1h, *w1l, *w2h, *w2l;
    cudaGetSymbolAddress((void**)&xnh,  g_xnh);  cudaGetSymbolAddress((void**)&xnl,  g_xnl);
    cudaGetSymbolAddress((void**)&atth, g_atth); cudaGetSymbolAddress((void**)&attl, g_attl);
    cudaGetSymbolAddress((void**)&ln2h, g_ln2h); cudaGetSymbolAddress((void**)&ln2l, g_ln2l);
    cudaGetSymbolAddress((void**)&h1h,  g_h1h);  cudaGetSymbolAddress((void**)&h1l,  g_h1l);
    cudaGetSymbolAddress((void**)&wqh, g_wqh);   cudaGetSymbolAddress((void**)&wql, g_wql);
    cudaGetSymbolAddress((void**)&wkh, g_wkh);   cudaGetSymbolAddress((void**)&wkl, g_wkl);
    cudaGetSymbolAddress((void**)&wvh, g_wvh);   cudaGetSymbolAddress((void**)&wvl, g_wvl);
    cudaGetSymbolAddress((void**)&woh, g_woh);   cudaGetSymbolAddress((void**)&wol, g_wol);
    cudaGetSymbolAddress((void**)&w1h, g_w1h);   cudaGetSymbolAddress((void**)&w1l, g_w1l);
    cudaGetSymbolAddress((void**)&w2h, g_w2h);   cudaGetSymbolAddress((void**)&w2l, g_w2l);

    cudaFuncSetAttribute(gemm_bf16<0>, cudaFuncAttributeMaxDynamicSharedMemorySize, GSMEMB);
    cudaFuncSetAttribute(gemm_bf16<1>, cudaFuncAttributeMaxDynamicSharedMemorySize, GSMEMB);
    cudaFuncSetAttribute(gemm_bf16<2>, cudaFuncAttributeMaxDynamicSharedMemorySize, GSMEMB);
    cudaFuncSetAttribute(gemm_bf16<3>, cudaFuncAttributeMaxDynamicSharedMemorySize, GSMEMB);

    // 0) weight splits (vectorized)
    split4_kernel<<<DD * DD / 1024, 256>>>((const float4*)Wq,   (__nv_bfloat162*)wqh, (__nv_bfloat162*)wql, DD * DD / 4);
    split4_kernel<<<DD * DD / 1024, 256>>>((const float4*)Wk,   (__nv_bfloat162*)wkh, (__nv_bfloat162*)wkl, DD * DD / 4);
    split4_kernel<<<DD * DD / 1024, 256>>>((const float4*)Wv,   (__nv_bfloat162*)wvh, (__nv_bfloat162*)wvl, DD * DD / 4);
    split4_kernel<<<DD * DD / 1024, 256>>>((const float4*)W_out,(__nv_bfloat162*)woh, (__nv_bfloat162*)wol, DD * DD / 4);
    split4_kernel<<<DFF * DD / 1024, 256>>>((const float4*)W1,  (__nv_bfloat162*)w1h, (__nv_bfloat162*)w1l, DFF * DD / 4);
    split4_kernel<<<DD * DFF / 1024, 256>>>((const float4*)W2,  (__nv_bfloat162*)w2h, (__nv_bfloat162*)w2l, DD * DFF / 4);
    // 1) pre-LN -> bf16 split
    ln_bf16_kernel<<<BNROWS, 128>>>(x, ng, nb, xnh, xnl);
    // 2) Q,K,V projections
    gemm_bf16<0><<<dim3(DD / 128, BNROWS / 128), 256, GSMEMB>>>(xnh, xnl, wqh, wql, bq, nullptr, nullptr, pq, nullptr, nullptr, BNROWS, DD, DD);
    gemm_bf16<0><<<dim3(DD / 128, BNROWS / 128), 256, GSMEMB>>>(xnh, xnl, wkh, wkl, bk, nullptr, nullptr, pk, nullptr, nullptr, BNROWS, DD, DD);
    gemm_bf16<0><<<dim3(DD / 128, BNROWS / 128), 256, GSMEMB>>>(xnh, xnl, wvh, wvl, bv, nullptr, nullptr, pv, nullptr, nullptr, BNROWS, DD, DD);
    // 3) per-edge bias
    edge_bias_kernel<<<(BB * EE) / 8, 256>>>(rel, geo, W_eb, b_eb, geog, geob, W_geo, b_geo);
    // 4) winner map + neighbor compaction
    wmap_init_kernel<<<(BB * NNODE * NNODE) / 256, 256>>>();
    wmap_scatter_kernel<<<(BB * EE) / 256, 256>>>(edges, emask);
    nbr_kernel<<<(BB * NNODE) / 8, 256>>>(nmask);
    // 5) sparse attention
    attn_sparse_kernel<<<BB * NNODE, 256>>>();
    // 6) output projection + residual
    gemm_bf16<1><<<dim3(DD / 128, BNROWS / 128), 256, GSMEMB>>>(atth, attl, woh, wol, b_out, x, nullptr, px2, nullptr, nullptr, BNROWS, DD, DD);
    // 7) FF block
    ln_bf16_kernel<<<BNROWS, 128>>>(px2, fg, fb, ln2h, ln2l);
    gemm_bf16<2><<<dim3(DFF / 128, BNROWS / 128), 256, GSMEMB>>>(ln2h, ln2l, w1h, w1l, b1, nullptr, nullptr, nullptr, h1h, h1l, BNROWS, DFF, DD);
    gemm_bf16<3><<<dim3(DD / 128, BNROWS / 128), 256, GSMEMB>>>(h1h, h1l, w2h, w2l, b2, px2, nmask, out, nullptr, nullptr, BNROWS, DD, DFF);
}

// round 11
// speedup vs baseline: 1.7129x; 1.0350x over previous
#include <cuda_runtime.h>
#include <cuda_bf16.h>
#include <math.h>
#include <float.h>
#include <stdint.h>

// Problem constants
#define BB    32
#define NNODE 256
#define DD    512
#define HH    8
#define EE    1024
#define EDIM  256
#define GDIM  64
#define HDIM  64
#define BNROWS (BB*NNODE)   // 8192
#define DFF   2048

// ---------------- scratch (device globals; no runtime alloc) ----------------
__device__ float g_q  [BNROWS*DD];
__device__ float g_k  [BNROWS*DD];
__device__ float g_v  [BNROWS*DD];
__device__ float g_x2 [BNROWS*DD];
__device__ float g_ebias[BB*EE*HH];
__device__ int   g_wmap[BB*NNODE*NNODE];
__device__ int   g_nbr [BB*NNODE*NNODE];
__device__ int   g_cnt [BB*NNODE];

// pre-split bf16 hi/lo activation + weight buffers
__device__ __nv_bfloat16 g_xnh [BNROWS*DD],  g_xnl [BNROWS*DD];
__device__ __nv_bfloat16 g_atth[BNROWS*DD],  g_attl[BNROWS*DD];
__device__ __nv_bfloat16 g_ln2h[BNROWS*DD],  g_ln2l[BNROWS*DD];
__device__ __nv_bfloat16 g_h1h [BNROWS*DFF], g_h1l [BNROWS*DFF];
__device__ __nv_bfloat16 g_wqh[DD*DD], g_wql[DD*DD];
__device__ __nv_bfloat16 g_wkh[DD*DD], g_wkl[DD*DD];
__device__ __nv_bfloat16 g_wvh[DD*DD], g_wvl[DD*DD];
__device__ __nv_bfloat16 g_woh[DD*DD], g_wol[DD*DD];
__device__ __nv_bfloat16 g_w1h[DFF*DD], g_w1l[DFF*DD];
__device__ __nv_bfloat16 g_w2h[DD*DFF], g_w2l[DD*DFF];

// ---------------- fused fp32 -> bf16 hi/lo split over all 6 weight tensors ----------------
struct SplitJobs {
    const float4* src[6];
    __nv_bfloat162* h[6];
    __nv_bfloat162* l[6];
    int cum[7];           // cumulative sizes in float4 units
};

__global__ void split_all_kernel(SplitJobs jobs) {
    int idx = blockIdx.x * 256 + threadIdx.x;
    if (idx >= jobs.cum[6]) return;
    int j = 0;
#pragma unroll
    for (int t = 1; t < 6; t++) j += (idx >= jobs.cum[t]);
    int i = idx - jobs.cum[j];
    float4 v = jobs.src[j][i];
    __nv_bfloat16 h0 = __float2bfloat16_rn(v.x), h1 = __float2bfloat16_rn(v.y);
    __nv_bfloat16 h2 = __float2bfloat16_rn(v.z), h3 = __float2bfloat16_rn(v.w);
    jobs.h[j][2 * i]     = __nv_bfloat162(h0, h1);
    jobs.h[j][2 * i + 1] = __nv_bfloat162(h2, h3);
    jobs.l[j][2 * i]     = __nv_bfloat162(__float2bfloat16_rn(v.x - __bfloat162float(h0)),
                                          __float2bfloat16_rn(v.y - __bfloat162float(h1)));
    jobs.l[j][2 * i + 1] = __nv_bfloat162(__float2bfloat16_rn(v.z - __bfloat162float(h2)),
                                          __float2bfloat16_rn(v.w - __bfloat162float(h3)));
}

// ---------------- LayerNorm -> bf16 hi/lo ----------------
__global__ void ln_bf16_kernel(const float* __restrict__ x, const float* __restrict__ g,
                               const float* __restrict__ b, __nv_bfloat16* __restrict__ yh,
                               __nv_bfloat16* __restrict__ yl) {
    int row = blockIdx.x;
    const float* xr = x + (size_t)row * DD;
    int tid = threadIdx.x; // 128
    float v[4];
    float s = 0.f, s2 = 0.f;
#pragma unroll
    for (int i = 0; i < 4; i++) {
        v[i] = xr[tid + i * 128];
        s += v[i]; s2 += v[i] * v[i];
    }
    __shared__ float rs[4], rs2[4];
    for (int o = 16; o; o >>= 1) {
        s  += __shfl_xor_sync(~0u, s,  o);
        s2 += __shfl_xor_sync(~0u, s2, o);
    }
    int w = tid >> 5;
    if ((tid & 31) == 0) { rs[w] = s; rs2[w] = s2; }
    __syncthreads();
    s  = rs[0] + rs[1] + rs[2] + rs[3];
    s2 = rs2[0] + rs2[1] + rs2[2] + rs2[3];
    float mean = s * (1.f / DD);
    float var  = s2 * (1.f / DD) - mean * mean;
    float r = rsqrtf(var + 1e-5f);
#pragma unroll
    for (int i = 0; i < 4; i++) {
        int c = tid + i * 128;
        float y = (v[i] - mean) * r * g[c] + b[c];
        __nv_bfloat16 hh = __float2bfloat16_rn(y);
        yh[(size_t)row * DD + c] = hh;
        yl[(size_t)row * DD + c] = __float2bfloat16_rn(y - __bfloat162float(hh));
    }
}

// ========== pipelined tensor-core GEMM core (256 thr, 8 warps 4x2, 2-stage, 2 CTA/SM) ==========
#define PITCH 40   // bf16 per smem row (32 data + 8 pad) = 80 B
#define GSMEMB 81920

#define CP16(dst, src) \
    asm volatile("cp.async.cg.shared.global [%0], [%1], 16;" :: "r"(dst), "l"(src))

__device__ __forceinline__ void ldsm4(uint32_t a, uint32_t& r0, uint32_t& r1,
                                      uint32_t& r2, uint32_t& r3) {
    asm volatile("ldmatrix.sync.aligned.m8n8.x4.shared.b16 {%0,%1,%2,%3}, [%4];"
                 : "=r"(r0), "=r"(r1), "=r"(r2), "=r"(r3) : "r"(a));
}

__device__ __forceinline__ void mma16816(float (&d)[4], const uint32_t (&a)[4],
                                         const uint32_t* b) {
    asm volatile("mma.sync.aligned.m16n8k16.row.col.f32.bf16.bf16.f32 "
                 "{%0,%1,%2,%3}, {%4,%5,%6,%7}, {%8,%9}, {%0,%1,%2,%3};"
                 : "+f"(d[0]), "+f"(d[1]), "+f"(d[2]), "+f"(d[3])
                 : "r"(a[0]), "r"(a[1]), "r"(a[2]), "r"(a[3]), "r"(b[0]), "r"(b[1]));
}

// EPI: 0=bias->f32, 1=+res->f32, 2=silu->bf16 hi/lo, 3=+res,*rowscale->f32
template<int EPI>
__device__ __forceinline__ void gemm_body(
        const __nv_bfloat16* __restrict__ Ah_g, const __nv_bfloat16* __restrict__ Al_g,
        const __nv_bfloat16* __restrict__ Bh_g, const __nv_bfloat16* __restrict__ Bl_g,
        const float* __restrict__ bias, const float* __restrict__ res,
        const float* __restrict__ rowscale, float* __restrict__ C,
        __nv_bfloat16* __restrict__ Ch, __nv_bfloat16* __restrict__ Cl,
        int M, int Nout, int K, int bm0, int bn0) {
    extern __shared__ __align__(16) __nv_bfloat16 sm[];
    uint32_t smBase = (uint32_t)__cvta_generic_to_shared(sm);

    int tid = threadIdx.x;               // 256 = 8 warps (4x2)
    int warp = tid >> 5, lane = tid & 31;
    int wm = warp >> 1, wn = warp & 1;

    float acc[2][8][4];
#pragma unroll
    for (int i = 0; i < 2; i++)
#pragma unroll
        for (int j = 0; j < 8; j++)
#pragma unroll
            for (int r = 0; r < 4; r++) acc[i][j][r] = 0.f;

    int row0 = tid >> 2, cc0 = (tid & 3);
    int row1 = row0 + 64;

    int a_r  = lane & 15;
    int a_cb = (lane >> 4) << 4;
    uint32_t aOffH = (uint32_t)((wm * 32 + a_r) * (PITCH * 2) + a_cb);
    int b_r  = ((lane >> 4) & 1) * 8 + (lane & 7);
    int b_cb = ((lane >> 3) & 1) << 4;
    uint32_t bOffH = (uint32_t)((wn * 64 + b_r) * (PITCH * 2) + b_cb);

    auto issue_tile = [&](int s, int k0) {
        uint32_t st = smBase + (uint32_t)s * 40960u;
        uint32_t so0 = (uint32_t)((row0 * PITCH + cc0 * 8) * 2);
        uint32_t so1 = (uint32_t)((row1 * PITCH + cc0 * 8) * 2);
        size_t ga0 = (size_t)(bm0 + row0) * K + k0 + cc0 * 8;
        size_t ga1 = (size_t)(bm0 + row1) * K + k0 + cc0 * 8;
        size_t gb0 = (size_t)(bn0 + row0) * K + k0 + cc0 * 8;
        size_t gb1 = (size_t)(bn0 + row1) * K + k0 + cc0 * 8;
        CP16(st + so0,          Ah_g + ga0);
        CP16(st + so1,          Ah_g + ga1);
        CP16(st + 10240 + so0,  Al_g + ga0);
        CP16(st + 10240 + so1,  Al_g + ga1);
        CP16(st + 20480 + so0,  Bh_g + gb0);
        CP16(st + 20480 + so1,  Bh_g + gb1);
        CP16(st + 30720 + so0,  Bl_g + gb0);
        CP16(st + 30720 + so1,  Bl_g + gb1);
    };

    issue_tile(0, 0);
    asm volatile("cp.async.commit_group;");
    issue_tile(1, 32);
    asm volatile("cp.async.commit_group;");

    int ktiles = K >> 5;
#pragma unroll 1
    for (int t = 0; t < ktiles; t++) {
        int s = t & 1;
        asm volatile("cp.async.wait_group 1;");
        __syncthreads();

        uint32_t pAh = smBase + (uint32_t)s * 40960u;
        uint32_t pAl = pAh + 10240u;
        uint32_t pBh = pAh + 20480u;
        uint32_t pBl = pAh + 30720u;
#pragma unroll
        for (int ks = 0; ks < 2; ks++) {
            uint32_t kb = (uint32_t)(ks * 32);
            uint32_t ah[2][4], al[2][4];
#pragma unroll
            for (int mi = 0; mi < 2; mi++) {
                uint32_t off = aOffH + (uint32_t)(mi * 16 * PITCH * 2) + kb;
                ldsm4(pAh + off, ah[mi][0], ah[mi][1], ah[mi][2], ah[mi][3]);
                ldsm4(pAl + off, al[mi][0], al[mi][1], al[mi][2], al[mi][3]);
            }
#pragma unroll
            for (int bp = 0; bp < 4; bp++) {
                uint32_t off = bOffH + (uint32_t)(bp * 16 * PITCH * 2) + kb;
                uint32_t bh[2][2], bl[2][2];
                ldsm4(pBh + off, bh[0][0], bh[0][1], bh[1][0], bh[1][1]);
                ldsm4(pBl + off, bl[0][0], bl[0][1], bl[1][0], bl[1][1]);
#pragma unroll
                for (int mi = 0; mi < 2; mi++)
#pragma unroll
                    for (int q = 0; q < 2; q++) {
                        int ni = 2 * bp + q;
                        mma16816(acc[mi][ni], ah[mi], bh[q]);
                        mma16816(acc[mi][ni], ah[mi], bl[q]);
                        mma16816(acc[mi][ni], al[mi], bh[q]);
                    }
            }
        }
        __syncthreads();
        int nk = (t + 2) << 5;
        if (nk < K) issue_tile(s, nk);
        asm volatile("cp.async.commit_group;");
    }

    // epilogue
    int qr = lane >> 2, qc = (lane & 3) << 1;
#pragma unroll
    for (int mi = 0; mi < 2; mi++) {
        int m0 = bm0 + wm * 32 + mi * 16 + qr;
#pragma unroll
        for (int ni = 0; ni < 8; ni++) {
            int n = bn0 + wn * 64 + ni * 8 + qc;
            float b0 = bias[n], b1 = bias[n + 1];
#pragma unroll
            for (int rr = 0; rr < 2; rr++) {
                int m = m0 + rr * 8;
                float v0 = acc[mi][ni][rr * 2 + 0] + b0;
                float v1 = acc[mi][ni][rr * 2 + 1] + b1;
                if (EPI == 1 || EPI == 3) {
                    v0 += res[(size_t)m * Nout + n];
                    v1 += res[(size_t)m * Nout + n + 1];
                }
                if (EPI == 2) {
                    v0 = v0 / (1.f + expf(-v0));
                    v1 = v1 / (1.f + expf(-v1));
                    __nv_bfloat16 h0 = __float2bfloat16_rn(v0);
                    __nv_bfloat16 h1 = __float2bfloat16_rn(v1);
                    __nv_bfloat162 hh(h0, h1);
                    __nv_bfloat162 ll(__float2bfloat16_rn(v0 - __bfloat162float(h0)),
                                      __float2bfloat16_rn(v1 - __bfloat162float(h1)));
                    *(__nv_bfloat162*)(Ch + (size_t)m * Nout + n) = hh;
                    *(__nv_bfloat162*)(Cl + (size_t)m * Nout + n) = ll;
                } else {
                    if (EPI == 3) { float rsc = rowscale[m]; v0 *= rsc; v1 *= rsc; }
                    *(float2*)(C + (size_t)m * Nout + n) = make_float2(v0, v1);
                }
            }
        }
    }
}

template<int EPI>
__global__ void __launch_bounds__(256, 2)
gemm_bf16(const __nv_bfloat16* __restrict__ Ah_g, const __nv_bfloat16* __restrict__ Al_g,
          const __nv_bfloat16* __restrict__ Bh_g, const __nv_bfloat16* __restrict__ Bl_g,
          const float* __restrict__ bias, const float* __restrict__ res,
          const float* __restrict__ rowscale, float* __restrict__ C,
          __nv_bfloat16* __restrict__ Ch, __nv_bfloat16* __restrict__ Cl,
          int M, int Nout, int K) {
    gemm_body<EPI>(Ah_g, Al_g, Bh_g, Bl_g, bias, res, rowscale, C, Ch, Cl,
                   M, Nout, K, blockIdx.y * 128, blockIdx.x * 128);
}

// fused QKV: grid (12, 64); blockIdx.x selects weight (x>>2) and N-tile (x&3)
__global__ void __launch_bounds__(256, 2)
gemm_qkv(const __nv_bfloat16* __restrict__ Ah_g, const __nv_bfloat16* __restrict__ Al_g,
         const __nv_bfloat16* __restrict__ wqh, const __nv_bfloat16* __restrict__ wql,
         const __nv_bfloat16* __restrict__ wkh, const __nv_bfloat16* __restrict__ wkl,
         const __nv_bfloat16* __restrict__ wvh, const __nv_bfloat16* __restrict__ wvl,
         const float* __restrict__ bq, const float* __restrict__ bk,
         const float* __restrict__ bv,
         float* __restrict__ q, float* __restrict__ k, float* __restrict__ v) {
    int wsel = blockIdx.x >> 2;
    int bn0  = (blockIdx.x & 3) * 128;
    const __nv_bfloat16 *Bh, *Bl;
    const float* bias;
    float* C;
    if (wsel == 0)      { Bh = wqh; Bl = wql; bias = bq; C = q; }
    else if (wsel == 1) { Bh = wkh; Bl = wkl; bias = bk; C = k; }
    else                { Bh = wvh; Bl = wvl; bias = bv; C = v; }
    gemm_body<0>(Ah_g, Al_g, Bh, Bl, bias, nullptr, nullptr, C, nullptr, nullptr,
                 BNROWS, DD, DD, blockIdx.y * 128, bn0);
}

// ---------------- Edge bias: one warp per (b,e) ----------------
__global__ void edge_bias_kernel(const float* __restrict__ rel, const float* __restrict__ geo,
                                 const float* __restrict__ W_eb, const float* __restrict__ b_eb,
                                 const float* __restrict__ geog, const float* __restrict__ geob,
                                 const float* __restrict__ W_geo, const float* __restrict__ b_geo) {
    int warp = (blockIdx.x * blockDim.x + threadIdx.x) >> 5;
    int lane = threadIdx.x & 31;
    if (warp >= BB * EE) return;
    const float* re = rel + (size_t)warp * EDIM;
    const float* ge = geo + (size_t)warp * GDIM;
    float acc[8] = {0, 0, 0, 0, 0, 0, 0, 0};
#pragma unroll
    for (int it = 0; it < 8; it++) {
        int c = (it << 5) + lane;
        float xv = re[c];
#pragma unroll
        for (int h = 0; h < 8; h++) acc[h] += xv * W_eb[h * EDIM + c];
    }
    float g0 = ge[lane], g1 = ge[lane + 32];
    float s = g0 + g1, s2 = g0 * g0 + g1 * g1;
    for (int o = 16; o; o >>= 1) {
        s  += __shfl_xor_sync(~0u, s,  o);
        s2 += __shfl_xor_sync(~0u, s2, o);
    }
    float mean = s * (1.f / 64.f);
    float var  = s2 * (1.f / 64.f) - mean * mean;
    float r = rsqrtf(var + 1e-5f);
    float n0 = (g0 - mean) * r * geog[lane]      + geob[lane];
    float n1 = (g1 - mean) * r * geog[lane + 32] + geob[lane + 32];
#pragma unroll
    for (int h = 0; h < 8; h++)
        acc[h] += n0 * W_geo[h * GDIM + lane] + n1 * W_geo[h * GDIM + lane + 32];
#pragma unroll
    for (int h = 0; h < 8; h++) {
        float v = acc[h];
        for (int o = 16; o; o >>= 1) v += __shfl_xor_sync(~0u, v, o);
        if (lane == h) g_ebias[(size_t)warp * HH + h] = v + b_eb[h] + b_geo[h];
    }
}

// ---------------- winner map + scatter ----------------
__global__ void wmap_init_kernel() {
    int idx = blockIdx.x * 256 + threadIdx.x;
    g_wmap[idx] = -1;
}

__global__ void wmap_scatter_kernel(const int* __restrict__ edges, const float* __restrict__ emask) {
    int t = blockIdx.x * 256 + threadIdx.x;
    if (t >= BB * EE) return;
    int b = t >> 10, e = t & 1023;
    if (emask[t] > 0.5f) {
        int s = min(max(edges[2 * t], 0), NNODE - 1);
        int d = min(max(edges[2 * t + 1], 0), NNODE - 1);
        atomicMax(&g_wmap[b * 65536 + s * 256 + d], e);
        atomicMax(&g_wmap[b * 65536 + d * 256 + s], e + EE);
    }
}

// ---------------- neighbor-list compaction: one warp per (b,i) ----------------
__global__ void nbr_kernel(const float* __restrict__ nmask) {
    int gw = (blockIdx.x * blockDim.x + threadIdx.x) >> 5;
    int lane = threadIdx.x & 31;
    if (gw >= BB * NNODE) return;
    int b = gw >> 8, i = gw & 255;
    if (nmask[gw] == 0.f) {
        if (lane == 0) g_cnt[gw] = 0;
        return;
    }
    const int* wrow = g_wmap + (size_t)gw * 256;
    int* nrow = g_nbr + (size_t)gw * 256;
    int base = 0;
#pragma unroll
    for (int c = 0; c < 8; c++) {
        int j = c * 32 + lane;
        int w = wrow[j];
        bool valid = ((w >= 0) || (j == i)) && (nmask[b * 256 + j] != 0.f);
        unsigned m = __ballot_sync(~0u, valid);
        if (valid) {
            int pos = base + __popc(m & ((1u << lane) - 1));
            nrow[pos] = ((w + 1) << 8) | j;
        }
        base += __popc(m);
    }
    if (lane == 0) g_cnt[gw] = base;
}

// ---------------- sparse attention: block per (b,i), warp per head ----------------
__global__ void __launch_bounds__(256)
attn_sparse_kernel() {
    __shared__ float sc[HH][NNODE];
    __shared__ float qs[HH][64];

    int bi = blockIdx.x;
    int b = bi >> 8;
    int tid = threadIdx.x, h = tid >> 5, lane = tid & 31;
    size_t orow = (size_t)bi * DD + h * HDIM;

    int cnt = g_cnt[bi];
    if (cnt == 0) {
        __nv_bfloat162 z(__float2bfloat16_rn(0.f), __float2bfloat16_rn(0.f));
        int d0 = lane << 1;
        *(__nv_bfloat162*)&g_atth[orow + d0] = z;
        *(__nv_bfloat162*)&g_attl[orow + d0] = z;
        return;
    }

    qs[h][lane]      = g_q[orow + lane];
    qs[h][lane + 32] = g_q[orow + lane + 32];
    __syncwarp();

    const int* nrow = g_nbr + (size_t)bi * 256;
    const float* qh = qs[h];

    float mx = -FLT_MAX;
    for (int c0 = 0; c0 < cnt; c0 += 32) {
        int idx = c0 + lane;
        float s = -FLT_MAX;
        if (idx < cnt) {
            int packed = nrow[idx];
            int j = packed & 255;
            int w = (packed >> 8) - 1;
            const float* kr = g_k + (size_t)(b * NNODE + j) * DD + h * HDIM;
            float a = 0.f;
#pragma unroll
            for (int d4 = 0; d4 < 16; d4++) {
                float4 kv = *(const float4*)(kr + d4 * 4);
                a += kv.x * qh[d4 * 4] + kv.y * qh[d4 * 4 + 1]
                   + kv.z * qh[d4 * 4 + 2] + kv.w * qh[d4 * 4 + 3];
            }
            float bias = 0.f;
            if (w >= 0) {
                int e = (w >= EE) ? w - EE : w;
                bias = g_ebias[((size_t)b * EE + e) * HH + h];
            }
            s = a * 0.125f + bias;
            sc[h][idx] = s;
        }
        mx = fmaxf(mx, s);
    }
    for (int o = 16; o; o >>= 1) mx = fmaxf(mx, __shfl_xor_sync(~0u, mx, o));

    float sum = 0.f;
    for (int c0 = 0; c0 < cnt; c0 += 32) {
        int idx = c0 + lane;
        if (idx < cnt) {
            float p = expf(sc[h][idx] - mx);
            sc[h][idx] = p;
            sum += p;
        }
    }
    for (int o = 16; o; o >>= 1) sum += __shfl_xor_sync(~0u, sum, o);
    float inv = 1.f / sum;
    __syncwarp();

    int d0 = lane << 1;
    float o0 = 0.f, o1 = 0.f;
    for (int idx = 0; idx < cnt; idx++) {
        int j = nrow[idx] & 255;
        float p = sc[h][idx];
        const float* vr = g_v + (size_t)(b * NNODE + j) * DD + h * HDIM;
        float2 vv = *(const float2*)(vr + d0);
        o0 += p * vv.x;
        o1 += p * vv.y;
    }
    o0 *= inv; o1 *= inv;
    __nv_bfloat16 h0 = __float2bfloat16_rn(o0);
    __nv_bfloat16 h1 = __float2bfloat16_rn(o1);
    *(__nv_bfloat162*)&g_atth[orow + d0] = __nv_bfloat162(h0, h1);
    *(__nv_bfloat162*)&g_attl[orow + d0] =
        __nv_bfloat162(__float2bfloat16_rn(o0 - __bfloat162float(h0)),
                       __float2bfloat16_rn(o1 - __bfloat162float(h1)));
}

// ---------------- host launcher ----------------
extern "C" void kernel_launch(void* const* d_in, const int* in_sizes, int n_in,
                              void* d_out, int out_size) {
    const float* x     = (const float*)d_in[0];
    const float* nmask = (const float*)d_in[1];
    const int*   edges = (const int*)  d_in[2];
    const float* emask = (const float*)d_in[3];
    const float* rel   = (const float*)d_in[4];
    const float* geo   = (const float*)d_in[5];
    const float* Wq = (const float*)d_in[6];  const float* bq = (const float*)d_in[7];
    const float* Wk = (const float*)d_in[8];  const float* bk = (const float*)d_in[9];
    const float* Wv = (const float*)d_in[10]; const float* bv = (const float*)d_in[11];
    const float* W_eb = (const float*)d_in[12]; const float* b_eb = (const float*)d_in[13];
    const float* geog = (const float*)d_in[14]; const float* geob = (const float*)d_in[15];
    const float* W_geo = (const float*)d_in[16]; const float* b_geo = (const float*)d_in[17];
    const float* W_out = (const float*)d_in[18]; const float* b_out = (const float*)d_in[19];
    const float* ng = (const float*)d_in[20]; const float* nb = (const float*)d_in[21];
    const float* fg = (const float*)d_in[22]; const float* fb = (const float*)d_in[23];
    const float* W1 = (const float*)d_in[24]; const float* b1 = (const float*)d_in[25];
    const float* W2 = (const float*)d_in[26]; const float* b2 = (const float*)d_in[27];
    float* out = (float*)d_out;

    float *pq, *pk, *pv, *px2;
    cudaGetSymbolAddress((void**)&pq,  g_q);
    cudaGetSymbolAddress((void**)&pk,  g_k);
    cudaGetSymbolAddress((void**)&pv,  g_v);
    cudaGetSymbolAddress((void**)&px2, g_x2);
    __nv_bfloat16 *xnh, *xnl, *atth, *attl, *ln2h, *ln2l, *h1h, *h1l;
    __nv_bfloat16 *wqh, *wql, *wkh, *wkl, *wvh, *wvl, *woh, *wol, *w1h, *w1l, *w2h, *w2l;
    cudaGetSymbolAddress((void**)&xnh,  g_xnh);  cudaGetSymbolAddress((void**)&xnl,  g_xnl);
    cudaGetSymbolAddress((void**)&atth, g_atth); cudaGetSymbolAddress((void**)&attl, g_attl);
    cudaGetSymbolAddress((void**)&ln2h, g_ln2h); cudaGetSymbolAddress((void**)&ln2l, g_ln2l);
    cudaGetSymbolAddress((void**)&h1h,  g_h1h);  cudaGetSymbolAddress((void**)&h1l,  g_h1l);
    cudaGetSymbolAddress((void**)&wqh, g_wqh);   cudaGetSymbolAddress((void**)&wql, g_wql);
    cudaGetSymbolAddress((void**)&wkh, g_wkh);   cudaGetSymbolAddress((void**)&wkl, g_wkl);
    cudaGetSymbolAddress((void**)&wvh, g_wvh);   cudaGetSymbolAddress((void**)&wvl, g_wvl);
    cudaGetSymbolAddress((void**)&woh, g_woh);   cudaGetSymbolAddress((void**)&wol, g_wol);
    cudaGetSymbolAddress((void**)&w1h, g_w1h);   cudaGetSymbolAddress((void**)&w1l, g_w1l);
    cudaGetSymbolAddress((void**)&w2h, g_w2h);   cudaGetSymbolAddress((void**)&w2l, g_w2l);

    cudaFuncSetAttribute(gemm_qkv,     cudaFuncAttributeMaxDynamicSharedMemorySize, GSMEMB);
    cudaFuncSetAttribute(gemm_bf16<1>, cudaFuncAttributeMaxDynamicSharedMemorySize, GSMEMB);
    cudaFuncSetAttribute(gemm_bf16<2>, cudaFuncAttributeMaxDynamicSharedMemorySize, GSMEMB);
    cudaFuncSetAttribute(gemm_bf16<3>, cudaFuncAttributeMaxDynamicSharedMemorySize, GSMEMB);

    // 0) fused weight splits (one launch)
    SplitJobs jobs;
    int wsz = DD * DD / 4, fsz = DFF * DD / 4;
    jobs.src[0] = (const float4*)Wq;    jobs.h[0] = (__nv_bfloat162*)wqh; jobs.l[0] = (__nv_bfloat162*)wql;
    jobs.src[1] = (const float4*)Wk;    jobs.h[1] = (__nv_bfloat162*)wkh; jobs.l[1] = (__nv_bfloat162*)wkl;
    jobs.src[2] = (const float4*)Wv;    jobs.h[2] = (__nv_bfloat162*)wvh; jobs.l[2] = (__nv_bfloat162*)wvl;
    jobs.src[3] = (const float4*)W_out; jobs.h[3] = (__nv_bfloat162*)woh; jobs.l[3] = (__nv_bfloat162*)wol;
    jobs.src[4] = (const float4*)W1;    jobs.h[4] = (__nv_bfloat162*)w1h; jobs.l[4] = (__nv_bfloat162*)w1l;
    jobs.src[5] = (const float4*)W2;    jobs.h[5] = (__nv_bfloat162*)w2h; jobs.l[5] = (__nv_bfloat162*)w2l;
    jobs.cum[0] = 0;
    jobs.cum[1] = wsz;      jobs.cum[2] = 2 * wsz; jobs.cum[3] = 3 * wsz;
    jobs.cum[4] = 4 * wsz;  jobs.cum[5] = 4 * wsz + fsz; jobs.cum[6] = 4 * wsz + 2 * fsz;
    split_all_kernel<<<(jobs.cum[6] + 255) / 256, 256>>>(jobs);
    // 1) pre-LN -> bf16 split
    ln_bf16_kernel<<<BNROWS, 128>>>(x, ng, nb, xnh, xnl);
    // 2) fused Q,K,V projections (one launch, 768 blocks)
    gemm_qkv<<<dim3(12, BNROWS / 128), 256, GSMEMB>>>(xnh, xnl, wqh, wql, wkh, wkl, wvh, wvl,
                                                      bq, bk, bv, pq, pk, pv);
    // 3) per-edge bias
    edge_bias_kernel<<<(BB * EE) / 8, 256>>>(rel, geo, W_eb, b_eb, geog, geob, W_geo, b_geo);
    // 4) winner map + neighbor compaction
    wmap_init_kernel<<<(BB * NNODE * NNODE) / 256, 256>>>();
    wmap_scatter_kernel<<<(BB * EE) / 256, 256>>>(edges, emask);
    nbr_kernel<<<(BB * NNODE) / 8, 256>>>(nmask);
    // 5) sparse attention
    attn_sparse_kernel<<<BB * NNODE, 256>>>();
    // 6) output projection + residual
    gemm_bf16<1><<<dim3(DD / 128, BNROWS / 128), 256, GSMEMB>>>(atth, attl, woh, wol, b_out, x, nullptr, px2, nullptr, nullptr, BNROWS, DD, DD);
    // 7) FF block
    ln_bf16_kernel<<<BNROWS, 128>>>(px2, fg, fb, ln2h, ln2l);
    gemm_bf16<2><<<dim3(DFF / 128, BNROWS / 128), 256, GSMEMB>>>(ln2h, ln2l, w1h, w1l, b1, nullptr, nullptr, nullptr, h1h, h1l, BNROWS, DFF, DD);
    gemm_bf16<3><<<dim3(DD / 128, BNROWS / 128), 256, GSMEMB>>>(h1h, h1l, w2h, w2l, b2, px2, nmask, out, nullptr, nullptr, BNROWS, DD, DFF);
}

// round 12
// speedup vs baseline: 2.3021x; 1.3440x over previous
#include <cuda_runtime.h>
#include <cuda_fp16.h>
#include <math.h>
#include <float.h>
#include <stdint.h>

// Problem constants
#define BB    32
#define NNODE 256
#define DD    512
#define HH    8
#define EE    1024
#define EDIM  256
#define GDIM  64
#define HDIM  64
#define BNROWS (BB*NNODE)   // 8192
#define DFF   2048

// ---------------- scratch (device globals; no runtime alloc) ----------------
__device__ float g_q  [BNROWS*DD];
__device__ float g_k  [BNROWS*DD];
__device__ float g_v  [BNROWS*DD];
__device__ float g_x2 [BNROWS*DD];
__device__ float g_ebias[BB*EE*HH];
__device__ int   g_wmap[BB*NNODE*NNODE];
__device__ int   g_nbr [BB*NNODE*NNODE];
__device__ int   g_cnt [BB*NNODE];

// fp16 activations (single) + fp16 hi/lo weights
__device__ __half g_xn [BNROWS*DD];
__device__ __half g_att[BNROWS*DD];
__device__ __half g_ln2[BNROWS*DD];
__device__ __half g_h1 [BNROWS*DFF];
__device__ __half g_wqh[DD*DD], g_wql[DD*DD];
__device__ __half g_wkh[DD*DD], g_wkl[DD*DD];
__device__ __half g_wvh[DD*DD], g_wvl[DD*DD];
__device__ __half g_woh[DD*DD], g_wol[DD*DD];
__device__ __half g_w1h[DFF*DD], g_w1l[DFF*DD];
__device__ __half g_w2h[DD*DFF], g_w2l[DD*DFF];

// ---------------- fused fp32 -> fp16 hi/lo split over all 6 weight tensors ----------------
struct SplitJobs {
    const float4* src[6];
    __half2* h[6];
    __half2* l[6];
    int cum[7];           // cumulative sizes in float4 units
};

__global__ void split_all_kernel(SplitJobs jobs) {
    int idx = blockIdx.x * 256 + threadIdx.x;
    if (idx >= jobs.cum[6]) return;
    int j = 0;
#pragma unroll
    for (int t = 1; t < 6; t++) j += (idx >= jobs.cum[t]);
    int i = idx - jobs.cum[j];
    float4 v = jobs.src[j][i];
    __half h0 = __float2half_rn(v.x), h1 = __float2half_rn(v.y);
    __half h2 = __float2half_rn(v.z), h3 = __float2half_rn(v.w);
    jobs.h[j][2 * i]     = __half2(h0, h1);
    jobs.h[j][2 * i + 1] = __half2(h2, h3);
    jobs.l[j][2 * i]     = __half2(__float2half_rn(v.x - __half2float(h0)),
                                   __float2half_rn(v.y - __half2float(h1)));
    jobs.l[j][2 * i + 1] = __half2(__float2half_rn(v.z - __half2float(h2)),
                                   __float2half_rn(v.w - __half2float(h3)));
}

// ---------------- LayerNorm -> fp16 ----------------
__global__ void ln_h_kernel(const float* __restrict__ x, const float* __restrict__ g,
                            const float* __restrict__ b, __half* __restrict__ y) {
    int row = blockIdx.x;
    const float* xr = x + (size_t)row * DD;
    int tid = threadIdx.x; // 128
    float v[4];
    float s = 0.f, s2 = 0.f;
#pragma unroll
    for (int i = 0; i < 4; i++) {
        v[i] = xr[tid + i * 128];
        s += v[i]; s2 += v[i] * v[i];
    }
    __shared__ float rs[4], rs2[4];
    for (int o = 16; o; o >>= 1) {
        s  += __shfl_xor_sync(~0u, s,  o);
        s2 += __shfl_xor_sync(~0u, s2, o);
    }
    int w = tid >> 5;
    if ((tid & 31) == 0) { rs[w] = s; rs2[w] = s2; }
    __syncthreads();
    s  = rs[0] + rs[1] + rs[2] + rs[3];
    s2 = rs2[0] + rs2[1] + rs2[2] + rs2[3];
    float mean = s * (1.f / DD);
    float var  = s2 * (1.f / DD) - mean * mean;
    float r = rsqrtf(var + 1e-5f);
#pragma unroll
    for (int i = 0; i < 4; i++) {
        int c = tid + i * 128;
        float yv = (v[i] - mean) * r * g[c] + b[c];
        y[(size_t)row * DD + c] = __float2half_rn(yv);
    }
}

// ========== fp16 2-term tensor-core GEMM (256 thr, 8 warps 4x2, 2-stage, 2 CTA/SM) ==========
// D = A(fp16) @ (Wh + Wl)^T + bias
#define PITCH 40   // fp16 per smem row (32 data + 8 pad) = 80 B
#define GSTAGE 30720
#define GSMEMB (2*GSTAGE)

#define CP16(dst, src) \
    asm volatile("cp.async.cg.shared.global [%0], [%1], 16;" :: "r"(dst), "l"(src))

__device__ __forceinline__ void ldsm4(uint32_t a, uint32_t& r0, uint32_t& r1,
                                      uint32_t& r2, uint32_t& r3) {
    asm volatile("ldmatrix.sync.aligned.m8n8.x4.shared.b16 {%0,%1,%2,%3}, [%4];"
                 : "=r"(r0), "=r"(r1), "=r"(r2), "=r"(r3) : "r"(a));
}

__device__ __forceinline__ void mma16816(float (&d)[4], const uint32_t (&a)[4],
                                         const uint32_t* b) {
    asm volatile("mma.sync.aligned.m16n8k16.row.col.f32.f16.f16.f32 "
                 "{%0,%1,%2,%3}, {%4,%5,%6,%7}, {%8,%9}, {%0,%1,%2,%3};"
                 : "+f"(d[0]), "+f"(d[1]), "+f"(d[2]), "+f"(d[3])
                 : "r"(a[0]), "r"(a[1]), "r"(a[2]), "r"(a[3]), "r"(b[0]), "r"(b[1]));
}

// EPI: 0=bias->f32, 1=+res->f32, 2=silu->fp16, 3=+res,*rowscale->f32
template<int EPI>
__device__ __forceinline__ void gemm_body(
        const __half* __restrict__ A_g,
        const __half* __restrict__ Bh_g, const __half* __restrict__ Bl_g,
        const float* __restrict__ bias, const float* __restrict__ res,
        const float* __restrict__ rowscale, float* __restrict__ C,
        __half* __restrict__ Ch,
        int M, int Nout, int K, int bm0, int bn0) {
    extern __shared__ __align__(16) __half sm[];
    uint32_t smBase = (uint32_t)__cvta_generic_to_shared(sm);

    int tid = threadIdx.x;               // 256 = 8 warps (4x2)
    int warp = tid >> 5, lane = tid & 31;
    int wm = warp >> 1, wn = warp & 1;

    float acc[2][8][4];
#pragma unroll
    for (int i = 0; i < 2; i++)
#pragma unroll
        for (int j = 0; j < 8; j++)
#pragma unroll
            for (int r = 0; r < 4; r++) acc[i][j][r] = 0.f;

    int row0 = tid >> 2, cc0 = (tid & 3);
    int row1 = row0 + 64;

    int a_r  = lane & 15;
    int a_cb = (lane >> 4) << 4;
    uint32_t aOffH = (uint32_t)((wm * 32 + a_r) * (PITCH * 2) + a_cb);
    int b_r  = ((lane >> 4) & 1) * 8 + (lane & 7);
    int b_cb = ((lane >> 3) & 1) << 4;
    uint32_t bOffH = (uint32_t)((wn * 64 + b_r) * (PITCH * 2) + b_cb);

    auto issue_tile = [&](int s, int k0) {
        uint32_t st = smBase + (uint32_t)s * (uint32_t)GSTAGE;
        uint32_t so0 = (uint32_t)((row0 * PITCH + cc0 * 8) * 2);
        uint32_t so1 = (uint32_t)((row1 * PITCH + cc0 * 8) * 2);
        size_t ga0 = (size_t)(bm0 + row0) * K + k0 + cc0 * 8;
        size_t ga1 = (size_t)(bm0 + row1) * K + k0 + cc0 * 8;
        size_t gb0 = (size_t)(bn0 + row0) * K + k0 + cc0 * 8;
        size_t gb1 = (size_t)(bn0 + row1) * K + k0 + cc0 * 8;
        CP16(st + so0,          A_g  + ga0);
        CP16(st + so1,          A_g  + ga1);
        CP16(st + 10240 + so0,  Bh_g + gb0);
        CP16(st + 10240 + so1,  Bh_g + gb1);
        CP16(st + 20480 + so0,  Bl_g + gb0);
        CP16(st + 20480 + so1,  Bl_g + gb1);
    };

    issue_tile(0, 0);
    asm volatile("cp.async.commit_group;");
    issue_tile(1, 32);
    asm volatile("cp.async.commit_group;");

    int ktiles = K >> 5;
#pragma unroll 1
    for (int t = 0; t < ktiles; t++) {
        int s = t & 1;
        asm volatile("cp.async.wait_group 1;");
        __syncthreads();

        uint32_t pA  = smBase + (uint32_t)s * (uint32_t)GSTAGE;
        uint32_t pBh = pA + 10240u;
        uint32_t pBl = pA + 20480u;
#pragma unroll
        for (int ks = 0; ks < 2; ks++) {
            uint32_t kb = (uint32_t)(ks * 32);
            uint32_t ah[2][4];
#pragma unroll
            for (int mi = 0; mi < 2; mi++) {
                uint32_t off = aOffH + (uint32_t)(mi * 16 * PITCH * 2) + kb;
                ldsm4(pA + off, ah[mi][0], ah[mi][1], ah[mi][2], ah[mi][3]);
            }
#pragma unroll
            for (int bp = 0; bp < 4; bp++) {
                uint32_t off = bOffH + (uint32_t)(bp * 16 * PITCH * 2) + kb;
                uint32_t bh[2][2], bl[2][2];
                ldsm4(pBh + off, bh[0][0], bh[0][1], bh[1][0], bh[1][1]);
                ldsm4(pBl + off, bl[0][0], bl[0][1], bl[1][0], bl[1][1]);
#pragma unroll
                for (int mi = 0; mi < 2; mi++)
#pragma unroll
                    for (int q = 0; q < 2; q++) {
                        int ni = 2 * bp + q;
                        mma16816(acc[mi][ni], ah[mi], bh[q]);
                        mma16816(acc[mi][ni], ah[mi], bl[q]);
                    }
            }
        }
        __syncthreads();
        int nk = (t + 2) << 5;
        if (nk < K) issue_tile(s, nk);
        asm volatile("cp.async.commit_group;");
    }

    // epilogue
    int qr = lane >> 2, qc = (lane & 3) << 1;
#pragma unroll
    for (int mi = 0; mi < 2; mi++) {
        int m0 = bm0 + wm * 32 + mi * 16 + qr;
#pragma unroll
        for (int ni = 0; ni < 8; ni++) {
            int n = bn0 + wn * 64 + ni * 8 + qc;
            float b0 = bias[n], b1 = bias[n + 1];
#pragma unroll
            for (int rr = 0; rr < 2; rr++) {
                int m = m0 + rr * 8;
                float v0 = acc[mi][ni][rr * 2 + 0] + b0;
                float v1 = acc[mi][ni][rr * 2 + 1] + b1;
                if (EPI == 1 || EPI == 3) {
                    v0 += res[(size_t)m * Nout + n];
                    v1 += res[(size_t)m * Nout + n + 1];
                }
                if (EPI == 2) {
                    v0 = v0 / (1.f + expf(-v0));
                    v1 = v1 / (1.f + expf(-v1));
                    *(__half2*)(Ch + (size_t)m * Nout + n) =
                        __half2(__float2half_rn(v0), __float2half_rn(v1));
                } else {
                    if (EPI == 3) { float rsc = rowscale[m]; v0 *= rsc; v1 *= rsc; }
                    *(float2*)(C + (size_t)m * Nout + n) = make_float2(v0, v1);
                }
            }
        }
    }
}

template<int EPI>
__global__ void __launch_bounds__(256, 2)
gemm_h(const __half* __restrict__ A_g,
       const __half* __restrict__ Bh_g, const __half* __restrict__ Bl_g,
       const float* __restrict__ bias, const float* __restrict__ res,
       const float* __restrict__ rowscale, float* __restrict__ C,
       __half* __restrict__ Ch, int M, int Nout, int K) {
    gemm_body<EPI>(A_g, Bh_g, Bl_g, bias, res, rowscale, C, Ch,
                   M, Nout, K, blockIdx.y * 128, blockIdx.x * 128);
}

// fused QKV: grid (12, 64); blockIdx.x selects weight (x>>2) and N-tile (x&3)
__global__ void __launch_bounds__(256, 2)
gemm_qkv(const __half* __restrict__ A_g,
         const __half* __restrict__ wqh, const __half* __restrict__ wql,
         const __half* __restrict__ wkh, const __half* __restrict__ wkl,
         const __half* __restrict__ wvh, const __half* __restrict__ wvl,
         const float* __restrict__ bq, const float* __restrict__ bk,
         const float* __restrict__ bv,
         float* __restrict__ q, float* __restrict__ k, float* __restrict__ v) {
    int wsel = blockIdx.x >> 2;
    int bn0  = (blockIdx.x & 3) * 128;
    const __half *Bh, *Bl;
    const float* bias;
    float* C;
    if (wsel == 0)      { Bh = wqh; Bl = wql; bias = bq; C = q; }
    else if (wsel == 1) { Bh = wkh; Bl = wkl; bias = bk; C = k; }
    else                { Bh = wvh; Bl = wvl; bias = bv; C = v; }
    gemm_body<0>(A_g, Bh, Bl, bias, nullptr, nullptr, C, nullptr,
                 BNROWS, DD, DD, blockIdx.y * 128, bn0);
}

// ---------------- Edge bias: one warp per (b,e); weights staged in smem ----------------
__global__ void edge_bias_kernel(const float* __restrict__ rel, const float* __restrict__ geo,
                                 const float* __restrict__ W_eb, const float* __restrict__ b_eb,
                                 const float* __restrict__ geog, const float* __restrict__ geob,
                                 const float* __restrict__ W_geo, const float* __restrict__ b_geo) {
    __shared__ float sWeb[HH * EDIM];   // 8 KB
    __shared__ float sWgeo[HH * GDIM];  // 2 KB
    __shared__ float sgg[GDIM], sgb[GDIM];
    int tid = threadIdx.x;              // 256
    for (int i = tid; i < HH * EDIM; i += 256) sWeb[i] = W_eb[i];
    for (int i = tid; i < HH * GDIM; i += 256) sWgeo[i] = W_geo[i];
    if (tid < GDIM) { sgg[tid] = geog[tid]; sgb[tid] = geob[tid]; }
    __syncthreads();

    int warp = (blockIdx.x * blockDim.x + tid) >> 5;
    int lane = tid & 31;
    if (warp >= BB * EE) return;
    const float* re = rel + (size_t)warp * EDIM;
    const float* ge = geo + (size_t)warp * GDIM;
    float acc[8] = {0, 0, 0, 0, 0, 0, 0, 0};
#pragma unroll
    for (int it = 0; it < 8; it++) {
        int c = (it << 5) + lane;
        float xv = re[c];
#pragma unroll
        for (int h = 0; h < 8; h++) acc[h] += xv * sWeb[h * EDIM + c];
    }
    float g0 = ge[lane], g1 = ge[lane + 32];
    float s = g0 + g1, s2 = g0 * g0 + g1 * g1;
    for (int o = 16; o; o >>= 1) {
        s  += __shfl_xor_sync(~0u, s,  o);
        s2 += __shfl_xor_sync(~0u, s2, o);
    }
    float mean = s * (1.f / 64.f);
    float var  = s2 * (1.f / 64.f) - mean * mean;
    float r = rsqrtf(var + 1e-5f);
    float n0 = (g0 - mean) * r * sgg[lane]      + sgb[lane];
    float n1 = (g1 - mean) * r * sgg[lane + 32] + sgb[lane + 32];
#pragma unroll
    for (int h = 0; h < 8; h++)
        acc[h] += n0 * sWgeo[h * GDIM + lane] + n1 * sWgeo[h * GDIM + lane + 32];
#pragma unroll
    for (int h = 0; h < 8; h++) {
        float v = acc[h];
        for (int o = 16; o; o >>= 1) v += __shfl_xor_sync(~0u, v, o);
        if (lane == h) g_ebias[(size_t)warp * HH + h] = v + b_eb[h] + b_geo[h];
    }
}

// ---------------- winner map + scatter ----------------
__global__ void wmap_init_kernel() {
    int idx = blockIdx.x * 256 + threadIdx.x;
    g_wmap[idx] = -1;
}

__global__ void wmap_scatter_kernel(const int* __restrict__ edges, const float* __restrict__ emask) {
    int t = blockIdx.x * 256 + threadIdx.x;
    if (t >= BB * EE) return;
    int b = t >> 10, e = t & 1023;
    if (emask[t] > 0.5f) {
        int s = min(max(edges[2 * t], 0), NNODE - 1);
        int d = min(max(edges[2 * t + 1], 0), NNODE - 1);
        atomicMax(&g_wmap[b * 65536 + s * 256 + d], e);
        atomicMax(&g_wmap[b * 65536 + d * 256 + s], e + EE);
    }
}

// ---------------- neighbor-list compaction: one warp per (b,i) ----------------
__global__ void nbr_kernel(const float* __restrict__ nmask) {
    int gw = (blockIdx.x * blockDim.x + threadIdx.x) >> 5;
    int lane = threadIdx.x & 31;
    if (gw >= BB * NNODE) return;
    int b = gw >> 8, i = gw & 255;
    if (nmask[gw] == 0.f) {
        if (lane == 0) g_cnt[gw] = 0;
        return;
    }
    const int* wrow = g_wmap + (size_t)gw * 256;
    int* nrow = g_nbr + (size_t)gw * 256;
    int base = 0;
#pragma unroll
    for (int c = 0; c < 8; c++) {
        int j = c * 32 + lane;
        int w = wrow[j];
        bool valid = ((w >= 0) || (j == i)) && (nmask[b * 256 + j] != 0.f);
        unsigned m = __ballot_sync(~0u, valid);
        if (valid) {
            int pos = base + __popc(m & ((1u << lane) - 1));
            nrow[pos] = ((w + 1) << 8) | j;
        }
        base += __popc(m);
    }
    if (lane == 0) g_cnt[gw] = base;
}

// ---------------- sparse attention: block per (b,i), warp per head ----------------
__global__ void __launch_bounds__(256)
attn_sparse_kernel() {
    __shared__ float sc[HH][NNODE];
    __shared__ float qs[HH][64];

    int bi = blockIdx.x;
    int b = bi >> 8;
    int tid = threadIdx.x, h = tid >> 5, lane = tid & 31;
    size_t orow = (size_t)bi * DD + h * HDIM;

    int cnt = g_cnt[bi];
    int d0 = lane << 1;
    if (cnt == 0) {
        *(__half2*)&g_att[orow + d0] = __half2(__float2half_rn(0.f), __float2half_rn(0.f));
        return;
    }

    qs[h][lane]      = g_q[orow + lane];
    qs[h][lane + 32] = g_q[orow + lane + 32];
    __syncwarp();

    const int* nrow = g_nbr + (size_t)bi * 256;
    const float* qh = qs[h];

    float mx = -FLT_MAX;
    for (int c0 = 0; c0 < cnt; c0 += 32) {
        int idx = c0 + lane;
        float s = -FLT_MAX;
        if (idx < cnt) {
            int packed = nrow[idx];
            int j = packed & 255;
            int w = (packed >> 8) - 1;
            const float* kr = g_k + (size_t)(b * NNODE + j) * DD + h * HDIM;
            float a = 0.f;
#pragma unroll
            for (int d4 = 0; d4 < 16; d4++) {
                float4 kv = *(const float4*)(kr + d4 * 4);
                a += kv.x * qh[d4 * 4] + kv.y * qh[d4 * 4 + 1]
                   + kv.z * qh[d4 * 4 + 2] + kv.w * qh[d4 * 4 + 3];
            }
            float bias = 0.f;
            if (w >= 0) {
                int e = (w >= EE) ? w - EE : w;
                bias = g_ebias[((size_t)b * EE + e) * HH + h];
            }
            s = a * 0.125f + bias;
            sc[h][idx] = s;
        }
        mx = fmaxf(mx, s);
    }
    for (int o = 16; o; o >>= 1) mx = fmaxf(mx, __shfl_xor_sync(~0u, mx, o));

    float sum = 0.f;
    for (int c0 = 0; c0 < cnt; c0 += 32) {
        int idx = c0 + lane;
        if (idx < cnt) {
            float p = expf(sc[h][idx] - mx);
            sc[h][idx] = p;
            sum += p;
        }
    }
    for (int o = 16; o; o >>= 1) sum += __shfl_xor_sync(~0u, sum, o);
    float inv = 1.f / sum;
    __syncwarp();

    float o0 = 0.f, o1 = 0.f;
    for (int idx = 0; idx < cnt; idx++) {
        int j = nrow[idx] & 255;
        float p = sc[h][idx];
        const float* vr = g_v + (size_t)(b * NNODE + j) * DD + h * HDIM;
        float2 vv = *(const float2*)(vr + d0);
        o0 += p * vv.x;
        o1 += p * vv.y;
    }
    o0 *= inv; o1 *= inv;
    *(__half2*)&g_att[orow + d0] = __half2(__float2half_rn(o0), __float2half_rn(o1));
}

// ---------------- host launcher ----------------
extern "C" void kernel_launch(void* const* d_in, const int* in_sizes, int n_in,
                              void* d_out, int out_size) {
    const float* x     = (const float*)d_in[0];
    const float* nmask = (const float*)d_in[1];
    const int*   edges = (const int*)  d_in[2];
    const float* emask = (const float*)d_in[3];
    const float* rel   = (const float*)d_in[4];
    const float* geo   = (const float*)d_in[5];
    const float* Wq = (const float*)d_in[6];  const float* bq = (const float*)d_in[7];
    const float* Wk = (const float*)d_in[8];  const float* bk = (const float*)d_in[9];
    const float* Wv = (const float*)d_in[10]; const float* bv = (const float*)d_in[11];
    const float* W_eb = (const float*)d_in[12]; const float* b_eb = (const float*)d_in[13];
    const float* geog = (const float*)d_in[14]; const float* geob = (const float*)d_in[15];
    const float* W_geo = (const float*)d_in[16]; const float* b_geo = (const float*)d_in[17];
    const float* W_out = (const float*)d_in[18]; const float* b_out = (const float*)d_in[19];
    const float* ng = (const float*)d_in[20]; const float* nb = (const float*)d_in[21];
    const float* fg = (const float*)d_in[22]; const float* fb = (const float*)d_in[23];
    const float* W1 = (const float*)d_in[24]; const float* b1 = (const float*)d_in[25];
    const float* W2 = (const float*)d_in[26]; const float* b2 = (const float*)d_in[27];
    float* out = (float*)d_out;

    float *pq, *pk, *pv, *px2;
    cudaGetSymbolAddress((void**)&pq,  g_q);
    cudaGetSymbolAddress((void**)&pk,  g_k);
    cudaGetSymbolAddress((void**)&pv,  g_v);
    cudaGetSymbolAddress((void**)&px2, g_x2);
    __half *xn, *att, *ln2, *h1;
    __half *wqh, *wql, *wkh, *wkl, *wvh, *wvl, *woh, *wol, *w1h, *w1l, *w2h, *w2l;
    cudaGetSymbolAddress((void**)&xn,  g_xn);
    cudaGetSymbolAddress((void**)&att, g_att);
    cudaGetSymbolAddress((void**)&ln2, g_ln2);
    cudaGetSymbolAddress((void**)&h1,  g_h1);
    cudaGetSymbolAddress((void**)&wqh, g_wqh);  cudaGetSymbolAddress((void**)&wql, g_wql);
    cudaGetSymbolAddress((void**)&wkh, g_wkh);  cudaGetSymbolAddress((void**)&wkl, g_wkl);
    cudaGetSymbolAddress((void**)&wvh, g_wvh);  cudaGetSymbolAddress((void**)&wvl, g_wvl);
    cudaGetSymbolAddress((void**)&woh, g_woh);  cudaGetSymbolAddress((void**)&wol, g_wol);
    cudaGetSymbolAddress((void**)&w1h, g_w1h);  cudaGetSymbolAddress((void**)&w1l, g_w1l);
    cudaGetSymbolAddress((void**)&w2h, g_w2h);  cudaGetSymbolAddress((void**)&w2l, g_w2l);

    cudaFuncSetAttribute(gemm_qkv,   cudaFuncAttributeMaxDynamicSharedMemorySize, GSMEMB);
    cudaFuncSetAttribute(gemm_h<1>,  cudaFuncAttributeMaxDynamicSharedMemorySize, GSMEMB);
    cudaFuncSetAttribute(gemm_h<2>,  cudaFuncAttributeMaxDynamicSharedMemorySize, GSMEMB);
    cudaFuncSetAttribute(gemm_h<3>,  cudaFuncAttributeMaxDynamicSharedMemorySize, GSMEMB);

    // 0) fused weight splits (one launch)
    SplitJobs jobs;
    int wsz = DD * DD / 4, fsz = DFF * DD / 4;
    jobs.src[0] = (const float4*)Wq;    jobs.h[0] = (__half2*)wqh; jobs.l[0] = (__half2*)wql;
    jobs.src[1] = (const float4*)Wk;    jobs.h[1] = (__half2*)wkh; jobs.l[1] = (__half2*)wkl;
    jobs.src[2] = (const float4*)Wv;    jobs.h[2] = (__half2*)wvh; jobs.l[2] = (__half2*)wvl;
    jobs.src[3] = (const float4*)W_out; jobs.h[3] = (__half2*)woh; jobs.l[3] = (__half2*)wol;
    jobs.src[4] = (const float4*)W1;    jobs.h[4] = (__half2*)w1h; jobs.l[4] = (__half2*)w1l;
    jobs.src[5] = (const float4*)W2;    jobs.h[5] = (__half2*)w2h; jobs.l[5] = (__half2*)w2l;
    jobs.cum[0] = 0;
    jobs.cum[1] = wsz;      jobs.cum[2] = 2 * wsz; jobs.cum[3] = 3 * wsz;
    jobs.cum[4] = 4 * wsz;  jobs.cum[5] = 4 * wsz + fsz; jobs.cum[6] = 4 * wsz + 2 * fsz;
    split_all_kernel<<<(jobs.cum[6] + 255) / 256, 256>>>(jobs);
    // 1) pre-LN -> fp16
    ln_h_kernel<<<BNROWS, 128>>>(x, ng, nb, xn);
    // 2) fused Q,K,V projections (one launch, 768 blocks)
    gemm_qkv<<<dim3(12, BNROWS / 128), 256, GSMEMB>>>(xn, wqh, wql, wkh, wkl, wvh, wvl,
                                                      bq, bk, bv, pq, pk, pv);
    // 3) per-edge bias
    edge_bias_kernel<<<(BB * EE) / 8, 256>>>(rel, geo, W_eb, b_eb, geog, geob, W_geo, b_geo);
    // 4) winner map + neighbor compaction
    wmap_init_kernel<<<(BB * NNODE * NNODE) / 256, 256>>>();
    wmap_scatter_kernel<<<(BB * EE) / 256, 256>>>(edges, emask);
    nbr_kernel<<<(BB * NNODE) / 8, 256>>>(nmask);
    // 5) sparse attention (writes fp16 att)
    attn_sparse_kernel<<<BB * NNODE, 256>>>();
    // 6) output projection + residual
    gemm_h<1><<<dim3(DD / 128, BNROWS / 128), 256, GSMEMB>>>(att, woh, wol, b_out, x, nullptr, px2, nullptr, BNROWS, DD, DD);
    // 7) FF block
    ln_h_kernel<<<BNROWS, 128>>>(px2, fg, fb, ln2);
    gemm_h<2><<<dim3(DFF / 128, BNROWS / 128), 256, GSMEMB>>>(ln2, w1h, w1l, b1, nullptr, nullptr, nullptr, h1, BNROWS, DFF, DD);
    gemm_h<3><<<dim3(DD / 128, BNROWS / 128), 256, GSMEMB>>>(h1, w2h, w2l, b2, px2, nmask, out, nullptr, BNROWS, DD, DFF);
}

// round 13
// speedup vs baseline: 2.3031x; 1.0004x over previous
#include <cuda_runtime.h>
#include <cuda_fp16.h>
#include <math.h>
#include <float.h>
#include <stdint.h>

// Problem constants
#define BB    32
#define NNODE 256
#define DD    512
#define HH    8
#define EE    1024
#define EDIM  256
#define GDIM  64
#define HDIM  64
#define BNROWS (BB*NNODE)   // 8192
#define DFF   2048

// ---------------- scratch (device globals; no runtime alloc) ----------------
__device__ float g_q  [BNROWS*DD];
__device__ float g_k  [BNROWS*DD];
__device__ float g_v  [BNROWS*DD];
__device__ float g_x2 [BNROWS*DD];
__device__ float g_ebias[BB*EE*HH];
__device__ int   g_wmap[BB*NNODE*NNODE];
__device__ int   g_nbr [BB*NNODE*NNODE];
__device__ int   g_cnt [BB*NNODE];

// fp16 activations (single) + fp16 hi/lo weights
__device__ __half g_xn [BNROWS*DD];
__device__ __half g_att[BNROWS*DD];
__device__ __half g_ln2[BNROWS*DD];
__device__ __half g_h1 [BNROWS*DFF];
__device__ __half g_wqh[DD*DD], g_wql[DD*DD];
__device__ __half g_wkh[DD*DD], g_wkl[DD*DD];
__device__ __half g_wvh[DD*DD], g_wvl[DD*DD];
__device__ __half g_woh[DD*DD], g_wol[DD*DD];
__device__ __half g_w1h[DFF*DD], g_w1l[DFF*DD];
__device__ __half g_w2h[DD*DFF], g_w2l[DD*DFF];

// ---------------- fused fp32 -> fp16 hi/lo split over all 6 weight tensors ----------------
struct SplitJobs {
    const float4* src[6];
    __half2* h[6];
    __half2* l[6];
    int cum[7];           // cumulative sizes in float4 units
};

__global__ void split_all_kernel(SplitJobs jobs) {
    int idx = blockIdx.x * 256 + threadIdx.x;
    if (idx >= jobs.cum[6]) return;
    int j = 0;
#pragma unroll
    for (int t = 1; t < 6; t++) j += (idx >= jobs.cum[t]);
    int i = idx - jobs.cum[j];
    float4 v = jobs.src[j][i];
    __half h0 = __float2half_rn(v.x), h1 = __float2half_rn(v.y);
    __half h2 = __float2half_rn(v.z), h3 = __float2half_rn(v.w);
    jobs.h[j][2 * i]     = __half2(h0, h1);
    jobs.h[j][2 * i + 1] = __half2(h2, h3);
    jobs.l[j][2 * i]     = __half2(__float2half_rn(v.x - __half2float(h0)),
                                   __float2half_rn(v.y - __half2float(h1)));
    jobs.l[j][2 * i + 1] = __half2(__float2half_rn(v.z - __half2float(h2)),
                                   __float2half_rn(v.w - __half2float(h3)));
}

// ---------------- LayerNorm -> fp16 ----------------
__global__ void ln_h_kernel(const float* __restrict__ x, const float* __restrict__ g,
                            const float* __restrict__ b, __half* __restrict__ y) {
    int row = blockIdx.x;
    const float* xr = x + (size_t)row * DD;
    int tid = threadIdx.x; // 128
    float v[4];
    float s = 0.f, s2 = 0.f;
#pragma unroll
    for (int i = 0; i < 4; i++) {
        v[i] = xr[tid + i * 128];
        s += v[i]; s2 += v[i] * v[i];
    }
    __shared__ float rs[4], rs2[4];
    for (int o = 16; o; o >>= 1) {
        s  += __shfl_xor_sync(~0u, s,  o);
        s2 += __shfl_xor_sync(~0u, s2, o);
    }
    int w = tid >> 5;
    if ((tid & 31) == 0) { rs[w] = s; rs2[w] = s2; }
    __syncthreads();
    s  = rs[0] + rs[1] + rs[2] + rs[3];
    s2 = rs2[0] + rs2[1] + rs2[2] + rs2[3];
    float mean = s * (1.f / DD);
    float var  = s2 * (1.f / DD) - mean * mean;
    float r = rsqrtf(var + 1e-5f);
#pragma unroll
    for (int i = 0; i < 4; i++) {
        int c = tid + i * 128;
        float yv = (v[i] - mean) * r * g[c] + b[c];
        y[(size_t)row * DD + c] = __float2half_rn(yv);
    }
}

// ========== fp16 2-term tensor-core GEMM (256 thr, 8 warps 4x2, 2-stage, 2 CTA/SM) ==========
// D = A(fp16) @ (Wh + Wl)^T + bias
#define PITCH 40   // fp16 per smem row (32 data + 8 pad) = 80 B
#define GSTAGE 30720
#define GSMEMB (2*GSTAGE)

#define CP16(dst, src) \
    asm volatile("cp.async.cg.shared.global [%0], [%1], 16;" :: "r"(dst), "l"(src))

__device__ __forceinline__ void ldsm4(uint32_t a, uint32_t& r0, uint32_t& r1,
                                      uint32_t& r2, uint32_t& r3) {
    asm volatile("ldmatrix.sync.aligned.m8n8.x4.shared.b16 {%0,%1,%2,%3}, [%4];"
                 : "=r"(r0), "=r"(r1), "=r"(r2), "=r"(r3) : "r"(a));
}

__device__ __forceinline__ void mma16816(float (&d)[4], const uint32_t (&a)[4],
                                         const uint32_t* b) {
    asm volatile("mma.sync.aligned.m16n8k16.row.col.f32.f16.f16.f32 "
                 "{%0,%1,%2,%3}, {%4,%5,%6,%7}, {%8,%9}, {%0,%1,%2,%3};"
                 : "+f"(d[0]), "+f"(d[1]), "+f"(d[2]), "+f"(d[3])
                 : "r"(a[0]), "r"(a[1]), "r"(a[2]), "r"(a[3]), "r"(b[0]), "r"(b[1]));
}

// EPI: 0=bias->f32, 1=+res->f32, 2=silu->fp16, 3=+res,*rowscale->f32
template<int EPI>
__device__ __forceinline__ void gemm_body(
        const __half* __restrict__ A_g,
        const __half* __restrict__ Bh_g, const __half* __restrict__ Bl_g,
        const float* __restrict__ bias, const float* __restrict__ res,
        const float* __restrict__ rowscale, float* __restrict__ C,
        __half* __restrict__ Ch,
        int M, int Nout, int K, int bm0, int bn0) {
    extern __shared__ __align__(16) __half sm[];
    uint32_t smBase = (uint32_t)__cvta_generic_to_shared(sm);

    int tid = threadIdx.x;               // 256 = 8 warps (4x2)
    int warp = tid >> 5, lane = tid & 31;
    int wm = warp >> 1, wn = warp & 1;

    float acc[2][8][4];
#pragma unroll
    for (int i = 0; i < 2; i++)
#pragma unroll
        for (int j = 0; j < 8; j++)
#pragma unroll
            for (int r = 0; r < 4; r++) acc[i][j][r] = 0.f;

    int row0 = tid >> 2, cc0 = (tid & 3);
    int row1 = row0 + 64;

    int a_r  = lane & 15;
    int a_cb = (lane >> 4) << 4;
    uint32_t aOffH = (uint32_t)((wm * 32 + a_r) * (PITCH * 2) + a_cb);
    int b_r  = ((lane >> 4) & 1) * 8 + (lane & 7);
    int b_cb = ((lane >> 3) & 1) << 4;
    uint32_t bOffH = (uint32_t)((wn * 64 + b_r) * (PITCH * 2) + b_cb);

    auto issue_tile = [&](int s, int k0) {
        uint32_t st = smBase + (uint32_t)s * (uint32_t)GSTAGE;
        uint32_t so0 = (uint32_t)((row0 * PITCH + cc0 * 8) * 2);
        uint32_t so1 = (uint32_t)((row1 * PITCH + cc0 * 8) * 2);
        size_t ga0 = (size_t)(bm0 + row0) * K + k0 + cc0 * 8;
        size_t ga1 = (size_t)(bm0 + row1) * K + k0 + cc0 * 8;
        size_t gb0 = (size_t)(bn0 + row0) * K + k0 + cc0 * 8;
        size_t gb1 = (size_t)(bn0 + row1) * K + k0 + cc0 * 8;
        CP16(st + so0,          A_g  + ga0);
        CP16(st + so1,          A_g  + ga1);
        CP16(st + 10240 + so0,  Bh_g + gb0);
        CP16(st + 10240 + so1,  Bh_g + gb1);
        CP16(st + 20480 + so0,  Bl_g + gb0);
        CP16(st + 20480 + so1,  Bl_g + gb1);
    };

    issue_tile(0, 0);
    asm volatile("cp.async.commit_group;");
    issue_tile(1, 32);
    asm volatile("cp.async.commit_group;");

    int ktiles = K >> 5;
#pragma unroll 1
    for (int t = 0; t < ktiles; t++) {
        int s = t & 1;
        asm volatile("cp.async.wait_group 1;");
        __syncthreads();

        uint32_t pA  = smBase + (uint32_t)s * (uint32_t)GSTAGE;
        uint32_t pBh = pA + 10240u;
        uint32_t pBl = pA + 20480u;
#pragma unroll
        for (int ks = 0; ks < 2; ks++) {
            uint32_t kb = (uint32_t)(ks * 32);
            uint32_t ah[2][4];
#pragma unroll
            for (int mi = 0; mi < 2; mi++) {
                uint32_t off = aOffH + (uint32_t)(mi * 16 * PITCH * 2) + kb;
                ldsm4(pA + off, ah[mi][0], ah[mi][1], ah[mi][2], ah[mi][3]);
            }
#pragma unroll
            for (int bp = 0; bp < 4; bp++) {
                uint32_t off = bOffH + (uint32_t)(bp * 16 * PITCH * 2) + kb;
                uint32_t bh[2][2], bl[2][2];
                ldsm4(pBh + off, bh[0][0], bh[0][1], bh[1][0], bh[1][1]);
                ldsm4(pBl + off, bl[0][0], bl[0][1], bl[1][0], bl[1][1]);
#pragma unroll
                for (int mi = 0; mi < 2; mi++)
#pragma unroll
                    for (int q = 0; q < 2; q++) {
                        int ni = 2 * bp + q;
                        mma16816(acc[mi][ni], ah[mi], bh[q]);
                        mma16816(acc[mi][ni], ah[mi], bl[q]);
                    }
            }
        }
        __syncthreads();
        int nk = (t + 2) << 5;
        if (nk < K) issue_tile(s, nk);
        asm volatile("cp.async.commit_group;");
    }

    // epilogue
    int qr = lane >> 2, qc = (lane & 3) << 1;
#pragma unroll
    for (int mi = 0; mi < 2; mi++) {
        int m0 = bm0 + wm * 32 + mi * 16 + qr;
#pragma unroll
        for (int ni = 0; ni < 8; ni++) {
            int n = bn0 + wn * 64 + ni * 8 + qc;
            float b0 = bias[n], b1 = bias[n + 1];
#pragma unroll
            for (int rr = 0; rr < 2; rr++) {
                int m = m0 + rr * 8;
                float v0 = acc[mi][ni][rr * 2 + 0] + b0;
                float v1 = acc[mi][ni][rr * 2 + 1] + b1;
                if (EPI == 1 || EPI == 3) {
                    v0 += res[(size_t)m * Nout + n];
                    v1 += res[(size_t)m * Nout + n + 1];
                }
                if (EPI == 2) {
                    v0 = v0 / (1.f + expf(-v0));
                    v1 = v1 / (1.f + expf(-v1));
                    *(__half2*)(Ch + (size_t)m * Nout + n) =
                        __half2(__float2half_rn(v0), __float2half_rn(v1));
                } else {
                    if (EPI == 3) { float rsc = rowscale[m]; v0 *= rsc; v1 *= rsc; }
                    *(float2*)(C + (size_t)m * Nout + n) = make_float2(v0, v1);
                }
            }
        }
    }
}

template<int EPI>
__global__ void __launch_bounds__(256, 2)
gemm_h(const __half* __restrict__ A_g,
       const __half* __restrict__ Bh_g, const __half* __restrict__ Bl_g,
       const float* __restrict__ bias, const float* __restrict__ res,
       const float* __restrict__ rowscale, float* __restrict__ C,
       __half* __restrict__ Ch, int M, int Nout, int K) {
    gemm_body<EPI>(A_g, Bh_g, Bl_g, bias, res, rowscale, C, Ch,
                   M, Nout, K, blockIdx.y * 128, blockIdx.x * 128);
}

// fused QKV: grid (12, 64); blockIdx.x selects weight (x>>2) and N-tile (x&3)
__global__ void __launch_bounds__(256, 2)
gemm_qkv(const __half* __restrict__ A_g,
         const __half* __restrict__ wqh, const __half* __restrict__ wql,
         const __half* __restrict__ wkh, const __half* __restrict__ wkl,
         const __half* __restrict__ wvh, const __half* __restrict__ wvl,
         const float* __restrict__ bq, const float* __restrict__ bk,
         const float* __restrict__ bv,
         float* __restrict__ q, float* __restrict__ k, float* __restrict__ v) {
    int wsel = blockIdx.x >> 2;
    int bn0  = (blockIdx.x & 3) * 128;
    const __half *Bh, *Bl;
    const float* bias;
    float* C;
    if (wsel == 0)      { Bh = wqh; Bl = wql; bias = bq; C = q; }
    else if (wsel == 1) { Bh = wkh; Bl = wkl; bias = bk; C = k; }
    else                { Bh = wvh; Bl = wvl; bias = bv; C = v; }
    gemm_body<0>(A_g, Bh, Bl, bias, nullptr, nullptr, C, nullptr,
                 BNROWS, DD, DD, blockIdx.y * 128, bn0);
}

// ---------------- Edge bias: one warp per (b,e); weights staged in smem ----------------
__global__ void edge_bias_kernel(const float* __restrict__ rel, const float* __restrict__ geo,
                                 const float* __restrict__ W_eb, const float* __restrict__ b_eb,
                                 const float* __restrict__ geog, const float* __restrict__ geob,
                                 const float* __restrict__ W_geo, const float* __restrict__ b_geo) {
    __shared__ float sWeb[HH * EDIM];   // 8 KB
    __shared__ float sWgeo[HH * GDIM];  // 2 KB
    __shared__ float sgg[GDIM], sgb[GDIM];
    int tid = threadIdx.x;              // 256
    for (int i = tid; i < HH * EDIM; i += 256) sWeb[i] = W_eb[i];
    for (int i = tid; i < HH * GDIM; i += 256) sWgeo[i] = W_geo[i];
    if (tid < GDIM) { sgg[tid] = geog[tid]; sgb[tid] = geob[tid]; }
    __syncthreads();

    int warp = (blockIdx.x * blockDim.x + tid) >> 5;
    int lane = tid & 31;
    if (warp >= BB * EE) return;
    const float* re = rel + (size_t)warp * EDIM;
    const float* ge = geo + (size_t)warp * GDIM;
    float acc[8] = {0, 0, 0, 0, 0, 0, 0, 0};
#pragma unroll
    for (int it = 0; it < 8; it++) {
        int c = (it << 5) + lane;
        float xv = re[c];
#pragma unroll
        for (int h = 0; h < 8; h++) acc[h] += xv * sWeb[h * EDIM + c];
    }
    float g0 = ge[lane], g1 = ge[lane + 32];
    float s = g0 + g1, s2 = g0 * g0 + g1 * g1;
    for (int o = 16; o; o >>= 1) {
        s  += __shfl_xor_sync(~0u, s,  o);
        s2 += __shfl_xor_sync(~0u, s2, o);
    }
    float mean = s * (1.f / 64.f);
    float var  = s2 * (1.f / 64.f) - mean * mean;
    float r = rsqrtf(var + 1e-5f);
    float n0 = (g0 - mean) * r * sgg[lane]      + sgb[lane];
    float n1 = (g1 - mean) * r * sgg[lane + 32] + sgb[lane + 32];
#pragma unroll
    for (int h = 0; h < 8; h++)
        acc[h] += n0 * sWgeo[h * GDIM + lane] + n1 * sWgeo[h * GDIM + lane + 32];
#pragma unroll
    for (int h = 0; h < 8; h++) {
        float v = acc[h];
        for (int o = 16; o; o >>= 1) v += __shfl_xor_sync(~0u, v, o);
        if (lane == h) g_ebias[(size_t)warp * HH + h] = v + b_eb[h] + b_geo[h];
    }
}

// ---------------- winner map + scatter ----------------
__global__ void wmap_init_kernel() {
    int idx = blockIdx.x * 256 + threadIdx.x;
    g_wmap[idx] = -1;
}

__global__ void wmap_scatter_kernel(const int* __restrict__ edges, const float* __restrict__ emask) {
    int t = blockIdx.x * 256 + threadIdx.x;
    if (t >= BB * EE) return;
    int b = t >> 10, e = t & 1023;
    if (emask[t] > 0.5f) {
        int s = min(max(edges[2 * t], 0), NNODE - 1);
        int d = min(max(edges[2 * t + 1], 0), NNODE - 1);
        atomicMax(&g_wmap[b * 65536 + s * 256 + d], e);
        atomicMax(&g_wmap[b * 65536 + d * 256 + s], e + EE);
    }
}

// ---------------- neighbor-list compaction: one warp per (b,i) ----------------
__global__ void nbr_kernel(const float* __restrict__ nmask) {
    int gw = (blockIdx.x * blockDim.x + threadIdx.x) >> 5;
    int lane = threadIdx.x & 31;
    if (gw >= BB * NNODE) return;
    int b = gw >> 8, i = gw & 255;
    if (nmask[gw] == 0.f) {
        if (lane == 0) g_cnt[gw] = 0;
        return;
    }
    const int* wrow = g_wmap + (size_t)gw * 256;
    int* nrow = g_nbr + (size_t)gw * 256;
    int base = 0;
#pragma unroll
    for (int c = 0; c < 8; c++) {
        int j = c * 32 + lane;
        int w = wrow[j];
        bool valid = ((w >= 0) || (j == i)) && (nmask[b * 256 + j] != 0.f);
        unsigned m = __ballot_sync(~0u, valid);
        if (valid) {
            int pos = base + __popc(m & ((1u << lane) - 1));
            nrow[pos] = ((w + 1) << 8) | j;
        }
        base += __popc(m);
    }
    if (lane == 0) g_cnt[gw] = base;
}

// ---------------- sparse attention: block per (b,i), warp per head ----------------
__global__ void __launch_bounds__(256)
attn_sparse_kernel() {
    __shared__ float sc[HH][NNODE];
    __shared__ float qs[HH][64];

    int bi = blockIdx.x;
    int b = bi >> 8;
    int tid = threadIdx.x, h = tid >> 5, lane = tid & 31;
    size_t orow = (size_t)bi * DD + h * HDIM;

    int cnt = g_cnt[bi];
    int d0 = lane << 1;
    if (cnt == 0) {
        *(__half2*)&g_att[orow + d0] = __half2(__float2half_rn(0.f), __float2half_rn(0.f));
        return;
    }

    qs[h][lane]      = g_q[orow + lane];
    qs[h][lane + 32] = g_q[orow + lane + 32];
    __syncwarp();

    const int* nrow = g_nbr + (size_t)bi * 256;
    const float* qh = qs[h];

    float mx = -FLT_MAX;
    for (int c0 = 0; c0 < cnt; c0 += 32) {
        int idx = c0 + lane;
        float s = -FLT_MAX;
        if (idx < cnt) {
            int packed = nrow[idx];
            int j = packed & 255;
            int w = (packed >> 8) - 1;
            const float* kr = g_k + (size_t)(b * NNODE + j) * DD + h * HDIM;
            float a = 0.f;
#pragma unroll
            for (int d4 = 0; d4 < 16; d4++) {
                float4 kv = *(const float4*)(kr + d4 * 4);
                a += kv.x * qh[d4 * 4] + kv.y * qh[d4 * 4 + 1]
                   + kv.z * qh[d4 * 4 + 2] + kv.w * qh[d4 * 4 + 3];
            }
            float bias = 0.f;
            if (w >= 0) {
                int e = (w >= EE) ? w - EE : w;
                bias = g_ebias[((size_t)b * EE + e) * HH + h];
            }
            s = a * 0.125f + bias;
            sc[h][idx] = s;
        }
        mx = fmaxf(mx, s);
    }
    for (int o = 16; o; o >>= 1) mx = fmaxf(mx, __shfl_xor_sync(~0u, mx, o));

    float sum = 0.f;
    for (int c0 = 0; c0 < cnt; c0 += 32) {
        int idx = c0 + lane;
        if (idx < cnt) {
            float p = expf(sc[h][idx] - mx);
            sc[h][idx] = p;
            sum += p;
        }
    }
    for (int o = 16; o; o >>= 1) sum += __shfl_xor_sync(~0u, sum, o);
    float inv = 1.f / sum;
    __syncwarp();

    float o0 = 0.f, o1 = 0.f;
    for (int idx = 0; idx < cnt; idx++) {
        int j = nrow[idx] & 255;
        float p = sc[h][idx];
        const float* vr = g_v + (size_t)(b * NNODE + j) * DD + h * HDIM;
        float2 vv = *(const float2*)(vr + d0);
        o0 += p * vv.x;
        o1 += p * vv.y;
    }
    o0 *= inv; o1 *= inv;
    *(__half2*)&g_att[orow + d0] = __half2(__float2half_rn(o0), __float2half_rn(o1));
}

// ---------------- host launcher ----------------
extern "C" void kernel_launch(void* const* d_in, const int* in_sizes, int n_in,
                              void* d_out, int out_size) {
    const float* x     = (const float*)d_in[0];
    const float* nmask = (const float*)d_in[1];
    const int*   edges = (const int*)  d_in[2];
    const float* emask = (const float*)d_in[3];
    const float* rel   = (const float*)d_in[4];
    const float* geo   = (const float*)d_in[5];
    const float* Wq = (const float*)d_in[6];  const float* bq = (const float*)d_in[7];
    const float* Wk = (const float*)d_in[8];  const float* bk = (const float*)d_in[9];
    const float* Wv = (const float*)d_in[10]; const float* bv = (const float*)d_in[11];
    const float* W_eb = (const float*)d_in[12]; const float* b_eb = (const float*)d_in[13];
    const float* geog = (const float*)d_in[14]; const float* geob = (const float*)d_in[15];
    const float* W_geo = (const float*)d_in[16]; const float* b_geo = (const float*)d_in[17];
    const float* W_out = (const float*)d_in[18]; const float* b_out = (const float*)d_in[19];
    const float* ng = (const float*)d_in[20]; const float* nb = (const float*)d_in[21];
    const float* fg = (const float*)d_in[22]; const float* fb = (const float*)d_in[23];
    const float* W1 = (const float*)d_in[24]; const float* b1 = (const float*)d_in[25];
    const float* W2 = (const float*)d_in[26]; const float* b2 = (const float*)d_in[27];
    float* out = (float*)d_out;

    float *pq, *pk, *pv, *px2;
    cudaGetSymbolAddress((void**)&pq,  g_q);
    cudaGetSymbolAddress((void**)&pk,  g_k);
    cudaGetSymbolAddress((void**)&pv,  g_v);
    cudaGetSymbolAddress((void**)&px2, g_x2);
    __half *xn, *att, *ln2, *h1;
    __half *wqh, *wql, *wkh, *wkl, *wvh, *wvl, *woh, *wol, *w1h, *w1l, *w2h, *w2l;
    cudaGetSymbolAddress((void**)&xn,  g_xn);
    cudaGetSymbolAddress((void**)&att, g_att);
    cudaGetSymbolAddress((void**)&ln2, g_ln2);
    cudaGetSymbolAddress((void**)&h1,  g_h1);
    cudaGetSymbolAddress((void**)&wqh, g_wqh);  cudaGetSymbolAddress((void**)&wql, g_wql);
    cudaGetSymbolAddress((void**)&wkh, g_wkh);  cudaGetSymbolAddress((void**)&wkl, g_wkl);
    cudaGetSymbolAddress((void**)&wvh, g_wvh);  cudaGetSymbolAddress((void**)&wvl, g_wvl);
    cudaGetSymbolAddress((void**)&woh, g_woh);  cudaGetSymbolAddress((void**)&wol, g_wol);
    cudaGetSymbolAddress((void**)&w1h, g_w1h);  cudaGetSymbolAddress((void**)&w1l, g_w1l);
    cudaGetSymbolAddress((void**)&w2h, g_w2h);  cudaGetSymbolAddress((void**)&w2l, g_w2l);

    cudaFuncSetAttribute(gemm_qkv,   cudaFuncAttributeMaxDynamicSharedMemorySize, GSMEMB);
    cudaFuncSetAttribute(gemm_h<1>,  cudaFuncAttributeMaxDynamicSharedMemorySize, GSMEMB);
    cudaFuncSetAttribute(gemm_h<2>,  cudaFuncAttributeMaxDynamicSharedMemorySize, GSMEMB);
    cudaFuncSetAttribute(gemm_h<3>,  cudaFuncAttributeMaxDynamicSharedMemorySize, GSMEMB);

    // 0) fused weight splits (one launch)
    SplitJobs jobs;
    int wsz = DD * DD / 4, fsz = DFF * DD / 4;
    jobs.src[0] = (const float4*)Wq;    jobs.h[0] = (__half2*)wqh; jobs.l[0] = (__half2*)wql;
    jobs.src[1] = (const float4*)Wk;    jobs.h[1] = (__half2*)wkh; jobs.l[1] = (__half2*)wkl;
    jobs.src[2] = (const float4*)Wv;    jobs.h[2] = (__half2*)wvh; jobs.l[2] = (__half2*)wvl;
    jobs.src[3] = (const float4*)W_out; jobs.h[3] = (__half2*)woh; jobs.l[3] = (__half2*)wol;
    jobs.src[4] = (const float4*)W1;    jobs.h[4] = (__half2*)w1h; jobs.l[4] = (__half2*)w1l;
    jobs.src[5] = (const float4*)W2;    jobs.h[5] = (__half2*)w2h; jobs.l[5] = (__half2*)w2l;
    jobs.cum[0] = 0;
    jobs.cum[1] = wsz;      jobs.cum[2] = 2 * wsz; jobs.cum[3] = 3 * wsz;
    jobs.cum[4] = 4 * wsz;  jobs.cum[5] = 4 * wsz + fsz; jobs.cum[6] = 4 * wsz + 2 * fsz;
    split_all_kernel<<<(jobs.cum[6] + 255) / 256, 256>>>(jobs);
    // 1) pre-LN -> fp16
    ln_h_kernel<<<BNROWS, 128>>>(x, ng, nb, xn);
    // 2) fused Q,K,V projections (one launch, 768 blocks)
    gemm_qkv<<<dim3(12, BNROWS / 128), 256, GSMEMB>>>(xn, wqh, wql, wkh, wkl, wvh, wvl,
                                                      bq, bk, bv, pq, pk, pv);
    // 3) per-edge bias
    edge_bias_kernel<<<(BB * EE) / 8, 256>>>(rel, geo, W_eb, b_eb, geog, geob, W_geo, b_geo);
    // 4) winner map + neighbor compaction
    wmap_init_kernel<<<(BB * NNODE * NNODE) / 256, 256>>>();
    wmap_scatter_kernel<<<(BB * EE) / 256, 256>>>(edges, emask);
    nbr_kernel<<<(BB * NNODE) / 8, 256>>>(nmask);
    // 5) sparse attention (writes fp16 att)
    attn_sparse_kernel<<<BB * NNODE, 256>>>();
    // 6) output projection + residual
    gemm_h<1><<<dim3(DD / 128, BNROWS / 128), 256, GSMEMB>>>(att, woh, wol, b_out, x, nullptr, px2, nullptr, BNROWS, DD, DD);
    // 7) FF block
    ln_h_kernel<<<BNROWS, 128>>>(px2, fg, fb, ln2);
    gemm_h<2><<<dim3(DFF / 128, BNROWS / 128), 256, GSMEMB>>>(ln2, w1h, w1l, b1, nullptr, nullptr, nullptr, h1, BNROWS, DFF, DD);
    gemm_h<3><<<dim3(DD / 128, BNROWS / 128), 256, GSMEMB>>>(h1, w2h, w2l, b2, px2, nmask, out, nullptr, BNROWS, DD, DFF);
}

// round 14
// speedup vs baseline: 3.1046x; 1.3480x over previous
#include <cuda_runtime.h>
#include <cuda_fp16.h>
#include <math.h>
#include <float.h>
#include <stdint.h>

// Problem constants
#define BB    32
#define NNODE 256
#define DD    512
#define HH    8
#define EE    1024
#define EDIM  256
#define GDIM  64
#define HDIM  64
#define BNROWS (BB*NNODE)   // 8192
#define DFF   2048

// ---------------- scratch (device globals; no runtime alloc) ----------------
__device__ float g_q  [BNROWS*DD];
__device__ float g_k  [BNROWS*DD];
__device__ float g_v  [BNROWS*DD];
__device__ float g_x2 [BNROWS*DD];
__device__ float g_ebias[BB*EE*HH];
__device__ int   g_wmap[BB*NNODE*NNODE];
__device__ int   g_nbr [BB*NNODE*NNODE];
__device__ int   g_cnt [BB*NNODE];

// fp16 activations + fp16 weights
__device__ __half g_xn [BNROWS*DD];
__device__ __half g_att[BNROWS*DD];
__device__ __half g_ln2[BNROWS*DD];
__device__ __half g_h1 [BNROWS*DFF];
__device__ __half g_wq[DD*DD], g_wk[DD*DD], g_wv[DD*DD], g_wo[DD*DD];
__device__ __half g_w1[DFF*DD], g_w2[DD*DFF];

// ---------------- fused fp32 -> fp16 cast over all 6 weight tensors ----------------
struct CastJobs {
    const float4* src[6];
    __half2* dst[6];
    int cum[7];           // cumulative sizes in float4 units
};

__global__ void cast_all_kernel(CastJobs jobs) {
    int idx = blockIdx.x * 256 + threadIdx.x;
    if (idx >= jobs.cum[6]) return;
    int j = 0;
#pragma unroll
    for (int t = 1; t < 6; t++) j += (idx >= jobs.cum[t]);
    int i = idx - jobs.cum[j];
    float4 v = jobs.src[j][i];
    jobs.dst[j][2 * i]     = __half2(__float2half_rn(v.x), __float2half_rn(v.y));
    jobs.dst[j][2 * i + 1] = __half2(__float2half_rn(v.z), __float2half_rn(v.w));
}

// ---------------- LayerNorm -> fp16 ----------------
__global__ void ln_h_kernel(const float* __restrict__ x, const float* __restrict__ g,
                            const float* __restrict__ b, __half* __restrict__ y) {
    int row = blockIdx.x;
    const float* xr = x + (size_t)row * DD;
    int tid = threadIdx.x; // 128
    float v[4];
    float s = 0.f, s2 = 0.f;
#pragma unroll
    for (int i = 0; i < 4; i++) {
        v[i] = xr[tid + i * 128];
        s += v[i]; s2 += v[i] * v[i];
    }
    __shared__ float rs[4], rs2[4];
    for (int o = 16; o; o >>= 1) {
        s  += __shfl_xor_sync(~0u, s,  o);
        s2 += __shfl_xor_sync(~0u, s2, o);
    }
    int w = tid >> 5;
    if ((tid & 31) == 0) { rs[w] = s; rs2[w] = s2; }
    __syncthreads();
    s  = rs[0] + rs[1] + rs[2] + rs[3];
    s2 = rs2[0] + rs2[1] + rs2[2] + rs2[3];
    float mean = s * (1.f / DD);
    float var  = s2 * (1.f / DD) - mean * mean;
    float r = rsqrtf(var + 1e-5f);
#pragma unroll
    for (int i = 0; i < 4; i++) {
        int c = tid + i * 128;
        float yv = (v[i] - mean) * r * g[c] + b[c];
        y[(size_t)row * DD + c] = __float2half_rn(yv);
    }
}

// ========== fp16 tensor-core GEMM (256 thr, 8 warps 4x2, 2-stage, 2 CTA/SM) ==========
// D = A(fp16) @ W(fp16)^T + bias
#define PITCH 40   // fp16 per smem row (32 data + 8 pad) = 80 B
#define GSTAGE 20480
#define GSMEMB (2*GSTAGE)

#define CP16(dst, src) \
    asm volatile("cp.async.cg.shared.global [%0], [%1], 16;" :: "r"(dst), "l"(src))

__device__ __forceinline__ void ldsm4(uint32_t a, uint32_t& r0, uint32_t& r1,
                                      uint32_t& r2, uint32_t& r3) {
    asm volatile("ldmatrix.sync.aligned.m8n8.x4.shared.b16 {%0,%1,%2,%3}, [%4];"
                 : "=r"(r0), "=r"(r1), "=r"(r2), "=r"(r3) : "r"(a));
}

__device__ __forceinline__ void mma16816(float (&d)[4], const uint32_t (&a)[4],
                                         const uint32_t* b) {
    asm volatile("mma.sync.aligned.m16n8k16.row.col.f32.f16.f16.f32 "
                 "{%0,%1,%2,%3}, {%4,%5,%6,%7}, {%8,%9}, {%0,%1,%2,%3};"
                 : "+f"(d[0]), "+f"(d[1]), "+f"(d[2]), "+f"(d[3])
                 : "r"(a[0]), "r"(a[1]), "r"(a[2]), "r"(a[3]), "r"(b[0]), "r"(b[1]));
}

// EPI: 0=bias->f32, 1=+res->f32, 2=silu->fp16, 3=+res,*rowscale->f32
template<int EPI>
__device__ __forceinline__ void gemm_body(
        const __half* __restrict__ A_g, const __half* __restrict__ B_g,
        const float* __restrict__ bias, const float* __restrict__ res,
        const float* __restrict__ rowscale, float* __restrict__ C,
        __half* __restrict__ Ch,
        int M, int Nout, int K, int bm0, int bn0) {
    extern __shared__ __align__(16) __half sm[];
    uint32_t smBase = (uint32_t)__cvta_generic_to_shared(sm);

    int tid = threadIdx.x;               // 256 = 8 warps (4x2)
    int warp = tid >> 5, lane = tid & 31;
    int wm = warp >> 1, wn = warp & 1;

    float acc[2][8][4];
#pragma unroll
    for (int i = 0; i < 2; i++)
#pragma unroll
        for (int j = 0; j < 8; j++)
#pragma unroll
            for (int r = 0; r < 4; r++) acc[i][j][r] = 0.f;

    int row0 = tid >> 2, cc0 = (tid & 3);
    int row1 = row0 + 64;

    int a_r  = lane & 15;
    int a_cb = (lane >> 4) << 4;
    uint32_t aOffH = (uint32_t)((wm * 32 + a_r) * (PITCH * 2) + a_cb);
    int b_r  = ((lane >> 4) & 1) * 8 + (lane & 7);
    int b_cb = ((lane >> 3) & 1) << 4;
    uint32_t bOffH = (uint32_t)((wn * 64 + b_r) * (PITCH * 2) + b_cb);

    auto issue_tile = [&](int s, int k0) {
        uint32_t st = smBase + (uint32_t)s * (uint32_t)GSTAGE;
        uint32_t so0 = (uint32_t)((row0 * PITCH + cc0 * 8) * 2);
        uint32_t so1 = (uint32_t)((row1 * PITCH + cc0 * 8) * 2);
        size_t ga0 = (size_t)(bm0 + row0) * K + k0 + cc0 * 8;
        size_t ga1 = (size_t)(bm0 + row1) * K + k0 + cc0 * 8;
        size_t gb0 = (size_t)(bn0 + row0) * K + k0 + cc0 * 8;
        size_t gb1 = (size_t)(bn0 + row1) * K + k0 + cc0 * 8;
        CP16(st + so0,          A_g + ga0);
        CP16(st + so1,          A_g + ga1);
        CP16(st + 10240 + so0,  B_g + gb0);
        CP16(st + 10240 + so1,  B_g + gb1);
    };

    issue_tile(0, 0);
    asm volatile("cp.async.commit_group;");
    issue_tile(1, 32);
    asm volatile("cp.async.commit_group;");

    int ktiles = K >> 5;
#pragma unroll 1
    for (int t = 0; t < ktiles; t++) {
        int s = t & 1;
        asm volatile("cp.async.wait_group 1;");
        __syncthreads();

        uint32_t pA = smBase + (uint32_t)s * (uint32_t)GSTAGE;
        uint32_t pB = pA + 10240u;
#pragma unroll
        for (int ks = 0; ks < 2; ks++) {
            uint32_t kb = (uint32_t)(ks * 32);
            uint32_t ah[2][4];
#pragma unroll
            for (int mi = 0; mi < 2; mi++) {
                uint32_t off = aOffH + (uint32_t)(mi * 16 * PITCH * 2) + kb;
                ldsm4(pA + off, ah[mi][0], ah[mi][1], ah[mi][2], ah[mi][3]);
            }
#pragma unroll
            for (int bp = 0; bp < 4; bp++) {
                uint32_t off = bOffH + (uint32_t)(bp * 16 * PITCH * 2) + kb;
                uint32_t bh[2][2];
                ldsm4(pB + off, bh[0][0], bh[0][1], bh[1][0], bh[1][1]);
#pragma unroll
                for (int mi = 0; mi < 2; mi++)
#pragma unroll
                    for (int q = 0; q < 2; q++)
                        mma16816(acc[mi][2 * bp + q], ah[mi], bh[q]);
            }
        }
        __syncthreads();
        int nk = (t + 2) << 5;
        if (nk < K) issue_tile(s, nk);
        asm volatile("cp.async.commit_group;");
    }

    // epilogue
    int qr = lane >> 2, qc = (lane & 3) << 1;
#pragma unroll
    for (int mi = 0; mi < 2; mi++) {
        int m0 = bm0 + wm * 32 + mi * 16 + qr;
#pragma unroll
        for (int ni = 0; ni < 8; ni++) {
            int n = bn0 + wn * 64 + ni * 8 + qc;
            float b0 = bias[n], b1 = bias[n + 1];
#pragma unroll
            for (int rr = 0; rr < 2; rr++) {
                int m = m0 + rr * 8;
                float v0 = acc[mi][ni][rr * 2 + 0] + b0;
                float v1 = acc[mi][ni][rr * 2 + 1] + b1;
                if (EPI == 1 || EPI == 3) {
                    v0 += res[(size_t)m * Nout + n];
                    v1 += res[(size_t)m * Nout + n + 1];
                }
                if (EPI == 2) {
                    v0 = v0 / (1.f + expf(-v0));
                    v1 = v1 / (1.f + expf(-v1));
                    *(__half2*)(Ch + (size_t)m * Nout + n) =
                        __half2(__float2half_rn(v0), __float2half_rn(v1));
                } else {
                    if (EPI == 3) { float rsc = rowscale[m]; v0 *= rsc; v1 *= rsc; }
                    *(float2*)(C + (size_t)m * Nout + n) = make_float2(v0, v1);
                }
            }
        }
    }
}

template<int EPI>
__global__ void __launch_bounds__(256, 2)
gemm_h(const __half* __restrict__ A_g, const __half* __restrict__ B_g,
       const float* __restrict__ bias, const float* __restrict__ res,
       const float* __restrict__ rowscale, float* __restrict__ C,
       __half* __restrict__ Ch, int M, int Nout, int K) {
    gemm_body<EPI>(A_g, B_g, bias, res, rowscale, C, Ch,
                   M, Nout, K, blockIdx.y * 128, blockIdx.x * 128);
}

// fused QKV: grid (12, 64); blockIdx.x selects weight (x>>2) and N-tile (x&3)
__global__ void __launch_bounds__(256, 2)
gemm_qkv(const __half* __restrict__ A_g,
         const __half* __restrict__ wq, const __half* __restrict__ wk,
         const __half* __restrict__ wv,
         const float* __restrict__ bq, const float* __restrict__ bk,
         const float* __restrict__ bv,
         float* __restrict__ q, float* __restrict__ k, float* __restrict__ v) {
    int wsel = blockIdx.x >> 2;
    int bn0  = (blockIdx.x & 3) * 128;
    const __half* B;
    const float* bias;
    float* C;
    if (wsel == 0)      { B = wq; bias = bq; C = q; }
    else if (wsel == 1) { B = wk; bias = bk; C = k; }
    else                { B = wv; bias = bv; C = v; }
    gemm_body<0>(A_g, B, bias, nullptr, nullptr, C, nullptr,
                 BNROWS, DD, DD, blockIdx.y * 128, bn0);
}

// ---------------- Edge bias: one warp per (b,e) ----------------
__global__ void edge_bias_kernel(const float* __restrict__ rel, const float* __restrict__ geo,
                                 const float* __restrict__ W_eb, const float* __restrict__ b_eb,
                                 const float* __restrict__ geog, const float* __restrict__ geob,
                                 const float* __restrict__ W_geo, const float* __restrict__ b_geo) {
    int warp = (blockIdx.x * blockDim.x + threadIdx.x) >> 5;
    int lane = threadIdx.x & 31;
    if (warp >= BB * EE) return;
    const float* re = rel + (size_t)warp * EDIM;
    const float* ge = geo + (size_t)warp * GDIM;
    float acc[8] = {0, 0, 0, 0, 0, 0, 0, 0};
#pragma unroll
    for (int it = 0; it < 8; it++) {
        int c = (it << 5) + lane;
        float xv = re[c];
#pragma unroll
        for (int h = 0; h < 8; h++) acc[h] += xv * W_eb[h * EDIM + c];
    }
    float g0 = ge[lane], g1 = ge[lane + 32];
    float s = g0 + g1, s2 = g0 * g0 + g1 * g1;
    for (int o = 16; o; o >>= 1) {
        s  += __shfl_xor_sync(~0u, s,  o);
        s2 += __shfl_xor_sync(~0u, s2, o);
    }
    float mean = s * (1.f / 64.f);
    float var  = s2 * (1.f / 64.f) - mean * mean;
    float r = rsqrtf(var + 1e-5f);
    float n0 = (g0 - mean) * r * geog[lane]      + geob[lane];
    float n1 = (g1 - mean) * r * geog[lane + 32] + geob[lane + 32];
#pragma unroll
    for (int h = 0; h < 8; h++)
        acc[h] += n0 * W_geo[h * GDIM + lane] + n1 * W_geo[h * GDIM + lane + 32];
#pragma unroll
    for (int h = 0; h < 8; h++) {
        float v = acc[h];
        for (int o = 16; o; o >>= 1) v += __shfl_xor_sync(~0u, v, o);
        if (lane == h) g_ebias[(size_t)warp * HH + h] = v + b_eb[h] + b_geo[h];
    }
}

// ---------------- winner map + scatter ----------------
__global__ void wmap_init_kernel() {
    int idx = blockIdx.x * 256 + threadIdx.x;
    g_wmap[idx] = -1;
}

__global__ void wmap_scatter_kernel(const int* __restrict__ edges, const float* __restrict__ emask) {
    int t = blockIdx.x * 256 + threadIdx.x;
    if (t >= BB * EE) return;
    int b = t >> 10, e = t & 1023;
    if (emask[t] > 0.5f) {
        int s = min(max(edges[2 * t], 0), NNODE - 1);
        int d = min(max(edges[2 * t + 1], 0), NNODE - 1);
        atomicMax(&g_wmap[b * 65536 + s * 256 + d], e);
        atomicMax(&g_wmap[b * 65536 + d * 256 + s], e + EE);
    }
}

// ---------------- neighbor-list compaction: one warp per (b,i) ----------------
__global__ void nbr_kernel(const float* __restrict__ nmask) {
    int gw = (blockIdx.x * blockDim.x + threadIdx.x) >> 5;
    int lane = threadIdx.x & 31;
    if (gw >= BB * NNODE) return;
    int b = gw >> 8, i = gw & 255;
    if (nmask[gw] == 0.f) {
        if (lane == 0) g_cnt[gw] = 0;
        return;
    }
    const int* wrow = g_wmap + (size_t)gw * 256;
    int* nrow = g_nbr + (size_t)gw * 256;
    int base = 0;
#pragma unroll
    for (int c = 0; c < 8; c++) {
        int j = c * 32 + lane;
        int w = wrow[j];
        bool valid = ((w >= 0) || (j == i)) && (nmask[b * 256 + j] != 0.f);
        unsigned m = __ballot_sync(~0u, valid);
        if (valid) {
            int pos = base + __popc(m & ((1u << lane) - 1));
            nrow[pos] = ((w + 1) << 8) | j;
        }
        base += __popc(m);
    }
    if (lane == 0) g_cnt[gw] = base;
}

// ---------------- sparse attention: block per (b,i), warp per head ----------------
__global__ void __launch_bounds__(256)
attn_sparse_kernel() {
    __shared__ float sc[HH][NNODE];
    __shared__ float qs[HH][64];

    int bi = blockIdx.x;
    int b = bi >> 8;
    int tid = threadIdx.x, h = tid >> 5, lane = tid & 31;
    size_t orow = (size_t)bi * DD + h * HDIM;

    int cnt = g_cnt[bi];
    int d0 = lane << 1;
    if (cnt == 0) {
        *(__half2*)&g_att[orow + d0] = __half2(__float2half_rn(0.f), __float2half_rn(0.f));
        return;
    }

    qs[h][lane]      = g_q[orow + lane];
    qs[h][lane + 32] = g_q[orow + lane + 32];
    __syncwarp();

    const int* nrow = g_nbr + (size_t)bi * 256;
    const float* qh = qs[h];

    float mx = -FLT_MAX;
    for (int c0 = 0; c0 < cnt; c0 += 32) {
        int idx = c0 + lane;
        float s = -FLT_MAX;
        if (idx < cnt) {
            int packed = nrow[idx];
            int j = packed & 255;
            int w = (packed >> 8) - 1;
            const float* kr = g_k + (size_t)(b * NNODE + j) * DD + h * HDIM;
            float a = 0.f;
#pragma unroll
            for (int d4 = 0; d4 < 16; d4++) {
                float4 kv = *(const float4*)(kr + d4 * 4);
                a += kv.x * qh[d4 * 4] + kv.y * qh[d4 * 4 + 1]
                   + kv.z * qh[d4 * 4 + 2] + kv.w * qh[d4 * 4 + 3];
            }
            float bias = 0.f;
            if (w >= 0) {
                int e = (w >= EE) ? w - EE : w;
                bias = g_ebias[((size_t)b * EE + e) * HH + h];
            }
            s = a * 0.125f + bias;
            sc[h][idx] = s;
        }
        mx = fmaxf(mx, s);
    }
    for (int o = 16; o; o >>= 1) mx = fmaxf(mx, __shfl_xor_sync(~0u, mx, o));

    float sum = 0.f;
    for (int c0 = 0; c0 < cnt; c0 += 32) {
        int idx = c0 + lane;
        if (idx < cnt) {
            float p = expf(sc[h][idx] - mx);
            sc[h][idx] = p;
            sum += p;
        }
    }
    for (int o = 16; o; o >>= 1) sum += __shfl_xor_sync(~0u, sum, o);
    float inv = 1.f / sum;
    __syncwarp();

    float o0 = 0.f, o1 = 0.f;
    for (int idx = 0; idx < cnt; idx++) {
        int j = nrow[idx] & 255;
        float p = sc[h][idx];
        const float* vr = g_v + (size_t)(b * NNODE + j) * DD + h * HDIM;
        float2 vv = *(const float2*)(vr + d0);
        o0 += p * vv.x;
        o1 += p * vv.y;
    }
    o0 *= inv; o1 *= inv;
    *(__half2*)&g_att[orow + d0] = __half2(__float2half_rn(o0), __float2half_rn(o1));
}

// ---------------- host launcher ----------------
extern "C" void kernel_launch(void* const* d_in, const int* in_sizes, int n_in,
                              void* d_out, int out_size) {
    const float* x     = (const float*)d_in[0];
    const float* nmask = (const float*)d_in[1];
    const int*   edges = (const int*)  d_in[2];
    const float* emask = (const float*)d_in[3];
    const float* rel   = (const float*)d_in[4];
    const float* geo   = (const float*)d_in[5];
    const float* Wq = (const float*)d_in[6];  const float* bq = (const float*)d_in[7];
    const float* Wk = (const float*)d_in[8];  const float* bk = (const float*)d_in[9];
    const float* Wv = (const float*)d_in[10]; const float* bv = (const float*)d_in[11];
    const float* W_eb = (const float*)d_in[12]; const float* b_eb = (const float*)d_in[13];
    const float* geog = (const float*)d_in[14]; const float* geob = (const float*)d_in[15];
    const float* W_geo = (const float*)d_in[16]; const float* b_geo = (const float*)d_in[17];
    const float* W_out = (const float*)d_in[18]; const float* b_out = (const float*)d_in[19];
    const float* ng = (const float*)d_in[20]; const float* nb = (const float*)d_in[21];
    const float* fg = (const float*)d_in[22]; const float* fb = (const float*)d_in[23];
    const float* W1 = (const float*)d_in[24]; const float* b1 = (const float*)d_in[25];
    const float* W2 = (const float*)d_in[26]; const float* b2 = (const float*)d_in[27];
    float* out = (float*)d_out;

    float *pq, *pk, *pv, *px2;
    cudaGetSymbolAddress((void**)&pq,  g_q);
    cudaGetSymbolAddress((void**)&pk,  g_k);
    cudaGetSymbolAddress((void**)&pv,  g_v);
    cudaGetSymbolAddress((void**)&px2, g_x2);
    __half *xn, *att, *ln2, *h1;
    __half *wq, *wk, *wv, *wo, *w1, *w2;
    cudaGetSymbolAddress((void**)&xn,  g_xn);
    cudaGetSymbolAddress((void**)&att, g_att);
    cudaGetSymbolAddress((void**)&ln2, g_ln2);
    cudaGetSymbolAddress((void**)&h1,  g_h1);
    cudaGetSymbolAddress((void**)&wq, g_wq);
    cudaGetSymbolAddress((void**)&wk, g_wk);
    cudaGetSymbolAddress((void**)&wv, g_wv);
    cudaGetSymbolAddress((void**)&wo, g_wo);
    cudaGetSymbolAddress((void**)&w1, g_w1);
    cudaGetSymbolAddress((void**)&w2, g_w2);

    cudaFuncSetAttribute(gemm_qkv,  cudaFuncAttributeMaxDynamicSharedMemorySize, GSMEMB);
    cudaFuncSetAttribute(gemm_h<1>, cudaFuncAttributeMaxDynamicSharedMemorySize, GSMEMB);
    cudaFuncSetAttribute(gemm_h<2>, cudaFuncAttributeMaxDynamicSharedMemorySize, GSMEMB);
    cudaFuncSetAttribute(gemm_h<3>, cudaFuncAttributeMaxDynamicSharedMemorySize, GSMEMB);

    // 0) fused weight casts (one launch)
    CastJobs jobs;
    int wsz = DD * DD / 4, fsz = DFF * DD / 4;
    jobs.src[0] = (const float4*)Wq;    jobs.dst[0] = (__half2*)wq;
    jobs.src[1] = (const float4*)Wk;    jobs.dst[1] = (__half2*)wk;
    jobs.src[2] = (const float4*)Wv;    jobs.dst[2] = (__half2*)wv;
    jobs.src[3] = (const float4*)W_out; jobs.dst[3] = (__half2*)wo;
    jobs.src[4] = (const float4*)W1;    jobs.dst[4] = (__half2*)w1;
    jobs.src[5] = (const float4*)W2;    jobs.dst[5] = (__half2*)w2;
    jobs.cum[0] = 0;
    jobs.cum[1] = wsz;      jobs.cum[2] = 2 * wsz; jobs.cum[3] = 3 * wsz;
    jobs.cum[4] = 4 * wsz;  jobs.cum[5] = 4 * wsz + fsz; jobs.cum[6] = 4 * wsz + 2 * fsz;
    cast_all_kernel<<<(jobs.cum[6] + 255) / 256, 256>>>(jobs);
    // 1) pre-LN -> fp16
    ln_h_kernel<<<BNROWS, 128>>>(x, ng, nb, xn);
    // 2) fused Q,K,V projections (one launch, 768 blocks)
    gemm_qkv<<<dim3(12, BNROWS / 128), 256, GSMEMB>>>(xn, wq, wk, wv, bq, bk, bv, pq, pk, pv);
    // 3) per-edge bias
    edge_bias_kernel<<<(BB * EE) / 8, 256>>>(rel, geo, W_eb, b_eb, geog, geob, W_geo, b_geo);
    // 4) winner map + neighbor compaction
    wmap_init_kernel<<<(BB * NNODE * NNODE) / 256, 256>>>();
    wmap_scatter_kernel<<<(BB * EE) / 256, 256>>>(edges, emask);
    nbr_kernel<<<(BB * NNODE) / 8, 256>>>(nmask);
    // 5) sparse attention (writes fp16 att)
    attn_sparse_kernel<<<BB * NNODE, 256>>>();
    // 6) output projection + residual
    gemm_h<1><<<dim3(DD / 128, BNROWS / 128), 256, GSMEMB>>>(att, wo, b_out, x, nullptr, px2, nullptr, BNROWS, DD, DD);
    // 7) FF block
    ln_h_kernel<<<BNROWS, 128>>>(px2, fg, fb, ln2);
    gemm_h<2><<<dim3(DFF / 128, BNROWS / 128), 256, GSMEMB>>>(ln2, w1, b1, nullptr, nullptr, nullptr, h1, BNROWS, DFF, DD);
    gemm_h<3><<<dim3(DD / 128, BNROWS / 128), 256, GSMEMB>>>(h1, w2, b2, px2, nmask, out, nullptr, BNROWS, DD, DFF);
}